// round 14
// baseline (speedup 1.0000x reference)
#include <cuda_runtime.h>
#include <math.h>

#define NN 51200      // nodes
#define EE 409600     // edges (without self loops)
#define BB 256        // batch
#define NHOST 13
#define IN_F 64
#define H1 256
#define H2 64
#define ZN 65536      // max(NN, BB*H1) — elements to zero
#define NB 200        // NN / 256 scan blocks

typedef unsigned long long u64;

// ---------------- scratch (static device globals; no runtime alloc) -------
__device__ int   d_cnt[NN];
__device__ int   d_off[NN + 1];
__device__ int   d_cur[NN];
__device__ int   d_csr[EE];
__device__ int   d_flag[NN];
__device__ int   d_ishost[NN];
__device__ int   d_list[NN];
__device__ int   d_nf;
__device__ int   d_bsum[NB];
__device__ int   d_bbase[NB];
__device__ float d_dinv[NN];
__device__ float d_xw[(size_t)NN * H1];    // dinv * (x @ W1)
__device__ float d_x1[(size_t)NN * H1];    // relu(agg1 + b1) on frontier rows
__device__ float d_xw2[(size_t)NN * H2];   // dinv * (x1 @ W2), frontier rows only
__device__ float d_x2h[(size_t)BB * NHOST * H2];
__device__ float d_g[(size_t)BB * H1];     // global state
__device__ float d_ls[(size_t)BB * NHOST * H1];   // attn logits
__device__ float d_fs[(size_t)BB * NHOST * H1];   // attn feats

// ---------------- zero ------------------------------------------------------
__global__ void k_zero() {
    int i = blockIdx.x * blockDim.x + threadIdx.x;
    if (i < NN) { d_cnt[i] = 0; d_flag[i] = 0; d_ishost[i] = 0; }
    if (i < BB * H1) d_g[i] = 0.f;
    if (i == 0) d_nf = 0;
}

__global__ void k_count_mh(const int* __restrict__ dst, const int* __restrict__ hidx) {
    int e = blockIdx.x * blockDim.x + threadIdx.x;
    if (e < EE) atomicAdd(&d_cnt[dst[e]], 1);
    if (e < BB * NHOST) {
        int n = hidx[e];
        d_ishost[n] = 1;
        d_flag[n] = 1;
    }
}

// ---------------- parallel 3-phase scan -------------------------------------
__global__ void k_scan1() {
    __shared__ int sh[256];
    int t = threadIdx.x;
    sh[t] = d_cnt[blockIdx.x * 256 + t];
    __syncthreads();
#pragma unroll
    for (int d = 128; d > 0; d >>= 1) {
        if (t < d) sh[t] += sh[t + d];
        __syncthreads();
    }
    if (t == 0) d_bsum[blockIdx.x] = sh[0];
}

__global__ void k_scan2() {
    __shared__ int sh[256];
    int t = threadIdx.x;
    int v = (t < NB) ? d_bsum[t] : 0;
    sh[t] = v;
    __syncthreads();
#pragma unroll
    for (int d = 1; d < 256; d <<= 1) {
        int x = sh[t];
        int add = (t >= d) ? sh[t - d] : 0;
        __syncthreads();
        sh[t] = x + add;
        __syncthreads();
    }
    if (t < NB) d_bbase[t] = sh[t] - v;  // exclusive
}

__global__ void k_scan3() {
    __shared__ int sh[256];
    int t = threadIdx.x;
    int i = blockIdx.x * 256 + t;
    int c = d_cnt[i];
    sh[t] = c;
    __syncthreads();
#pragma unroll
    for (int d = 1; d < 256; d <<= 1) {
        int x = sh[t];
        int add = (t >= d) ? sh[t - d] : 0;
        __syncthreads();
        sh[t] = x + add;
        __syncthreads();
    }
    int off = d_bbase[blockIdx.x] + sh[t] - c;
    d_off[i] = off;
    d_cur[i] = off;
    d_dinv[i] = rsqrtf((float)(c + 1));
    if (i == 0) d_off[NN] = EE;
}

__global__ void k_fill_me(const int* __restrict__ src, const int* __restrict__ dst) {
    int e = blockIdx.x * blockDim.x + threadIdx.x;
    if (e < EE) {
        int d = dst[e];
        int s = src[e];
        int p = atomicAdd(&d_cur[d], 1);
        d_csr[p] = s;
        if (d_ishost[d]) d_flag[s] = 1;
    }
}

__global__ void k_mklist() {
    int i = blockIdx.x * blockDim.x + threadIdx.x;
    if (i < NN && d_flag[i]) {
        int p = atomicAdd(&d_nf, 1);
        d_list[p] = i;
    }
}

// ---------------- GEMM1: xw = dinv * (x @ W1)  [51200,64]x[64,256] ---------
#define G1R 32
__global__ void k_gemm1(const float* __restrict__ x, const float* __restrict__ W1) {
    __shared__ float xs[IN_F][G1R + 2];
    int r0 = blockIdx.x * G1R;
    int t = threadIdx.x; // 256
    int rg = t >> 6;
    int cg = t & 63;
    for (int i = t; i < G1R * IN_F; i += 256) {
        int r = i >> 6, k = i & 63;
        xs[k][r] = x[(size_t)(r0 + r) * IN_F + k];
    }
    __syncthreads();
    u64 acc[4][4];
#pragma unroll
    for (int p = 0; p < 4; p++)
#pragma unroll
        for (int c = 0; c < 4; c++) acc[p][c] = 0ull;
    for (int k = 0; k < IN_F; k++) {
        float4 w4 = *reinterpret_cast<const float4*>(&W1[k * H1 + cg * 4]);
        u64 wd[4];
        asm("mov.b64 %0, {%1, %1};" : "=l"(wd[0]) : "f"(w4.x));
        asm("mov.b64 %0, {%1, %1};" : "=l"(wd[1]) : "f"(w4.y));
        asm("mov.b64 %0, {%1, %1};" : "=l"(wd[2]) : "f"(w4.z));
        asm("mov.b64 %0, {%1, %1};" : "=l"(wd[3]) : "f"(w4.w));
        u64 xp[4];
#pragma unroll
        for (int p = 0; p < 4; p++)
            xp[p] = *reinterpret_cast<const u64*>(&xs[k][rg * 8 + 2 * p]);
#pragma unroll
        for (int p = 0; p < 4; p++)
#pragma unroll
            for (int c = 0; c < 4; c++)
                asm("fma.rn.f32x2 %0, %1, %2, %0;" : "+l"(acc[p][c]) : "l"(xp[p]), "l"(wd[c]));
    }
#pragma unroll
    for (int p = 0; p < 4; p++) {
        float lo[4], hi[4];
#pragma unroll
        for (int c = 0; c < 4; c++)
            asm("mov.b64 {%0, %1}, %2;" : "=f"(lo[c]), "=f"(hi[c]) : "l"(acc[p][c]));
        int ra = r0 + rg * 8 + 2 * p;
        float da = d_dinv[ra], db = d_dinv[ra + 1];
        float4 oa = make_float4(da * lo[0], da * lo[1], da * lo[2], da * lo[3]);
        float4 ob = make_float4(db * hi[0], db * hi[1], db * hi[2], db * hi[3]);
        *reinterpret_cast<float4*>(&d_xw[(size_t)ra * H1 + cg * 4])       = oa;
        *reinterpret_cast<float4*>(&d_xw[(size_t)(ra + 1) * H1 + cg * 4]) = ob;
    }
}

// ---------------- layer-1 max aggregation (r12 proven form) ----------------
// One frontier node per block, early exit, 8-wide gather, no barriers.
__global__ void k_agg1(const float* __restrict__ b1) {
    int bi = blockIdx.x;
    if (bi >= d_nf) return;
    int i = d_list[bi];
    int t = threadIdx.x; // 256
    float m = d_xw[(size_t)i * H1 + t];
    int e0 = d_off[i], e1 = d_off[i + 1];
    int e = e0;
    for (; e + 8 <= e1; e += 8) {
        int s0 = __ldg(&d_csr[e]);
        int s1 = __ldg(&d_csr[e + 1]);
        int s2 = __ldg(&d_csr[e + 2]);
        int s3 = __ldg(&d_csr[e + 3]);
        int s4 = __ldg(&d_csr[e + 4]);
        int s5 = __ldg(&d_csr[e + 5]);
        int s6 = __ldg(&d_csr[e + 6]);
        int s7 = __ldg(&d_csr[e + 7]);
        float v0 = __ldg(&d_xw[(size_t)s0 * H1 + t]);
        float v1 = __ldg(&d_xw[(size_t)s1 * H1 + t]);
        float v2 = __ldg(&d_xw[(size_t)s2 * H1 + t]);
        float v3 = __ldg(&d_xw[(size_t)s3 * H1 + t]);
        float v4 = __ldg(&d_xw[(size_t)s4 * H1 + t]);
        float v5 = __ldg(&d_xw[(size_t)s5 * H1 + t]);
        float v6 = __ldg(&d_xw[(size_t)s6 * H1 + t]);
        float v7 = __ldg(&d_xw[(size_t)s7 * H1 + t]);
        float m0 = fmaxf(fmaxf(v0, v1), fmaxf(v2, v3));
        float m1 = fmaxf(fmaxf(v4, v5), fmaxf(v6, v7));
        m = fmaxf(m, fmaxf(m0, m1));
    }
    for (; e < e1; e++)
        m = fmaxf(m, __ldg(&d_xw[(size_t)__ldg(&d_csr[e]) * H1 + t]));
    d_x1[(size_t)i * H1 + t] = fmaxf(d_dinv[i] * m + b1[t], 0.f);
}

// ---------------- GEMM2 on frontier rows: xw2 = dinv * (x1 @ W2) -----------
#define G2R 128
__global__ void k_gemm2(const float* __restrict__ W2) {
    int r0 = blockIdx.x * G2R;
    int nf = d_nf;
    if (r0 >= nf) return;
    __shared__ float xs[64][G2R + 2];
    __shared__ int rows[G2R];
    int t = threadIdx.x;      // 256
    int rg = t >> 4;
    int cg = t & 15;
    if (t < G2R) rows[t] = d_list[min(r0 + t, nf - 1)];
    __syncthreads();
    u64 acc[4][4];
#pragma unroll
    for (int p = 0; p < 4; p++)
#pragma unroll
        for (int c = 0; c < 4; c++) acc[p][c] = 0ull;
    for (int kc = 0; kc < H1; kc += 64) {
        __syncthreads();
        for (int i = t; i < G2R * 64; i += 256) {
            int r = i >> 6, k = i & 63;
            xs[k][r] = d_x1[(size_t)rows[r] * H1 + kc + k];
        }
        __syncthreads();
        for (int k = 0; k < 64; k++) {
            float4 w4 = *reinterpret_cast<const float4*>(&W2[(kc + k) * H2 + cg * 4]);
            u64 wd[4];
            asm("mov.b64 %0, {%1, %1};" : "=l"(wd[0]) : "f"(w4.x));
            asm("mov.b64 %0, {%1, %1};" : "=l"(wd[1]) : "f"(w4.y));
            asm("mov.b64 %0, {%1, %1};" : "=l"(wd[2]) : "f"(w4.z));
            asm("mov.b64 %0, {%1, %1};" : "=l"(wd[3]) : "f"(w4.w));
            u64 xp[4];
#pragma unroll
            for (int p = 0; p < 4; p++)
                xp[p] = *reinterpret_cast<const u64*>(&xs[k][rg * 8 + 2 * p]);
#pragma unroll
            for (int p = 0; p < 4; p++)
#pragma unroll
                for (int c = 0; c < 4; c++)
                    asm("fma.rn.f32x2 %0, %1, %2, %0;" : "+l"(acc[p][c]) : "l"(xp[p]), "l"(wd[c]));
        }
    }
#pragma unroll
    for (int p = 0; p < 4; p++) {
        float lo[4], hi[4];
#pragma unroll
        for (int c = 0; c < 4; c++)
            asm("mov.b64 {%0, %1}, %2;" : "=f"(lo[c]), "=f"(hi[c]) : "l"(acc[p][c]));
        int rla = rg * 8 + 2 * p;
        int ga = rows[rla], gb2 = rows[rla + 1];
        float da = d_dinv[ga], db = d_dinv[gb2];
        float4 oa = make_float4(da * lo[0], da * lo[1], da * lo[2], da * lo[3]);
        float4 ob = make_float4(db * hi[0], db * hi[1], db * hi[2], db * hi[3]);
        *reinterpret_cast<float4*>(&d_xw2[(size_t)ga * H2 + cg * 4])  = oa;
        *reinterpret_cast<float4*>(&d_xw2[(size_t)gb2 * H2 + cg * 4]) = ob;
    }
}

// ---------------- layer-2 max aggregation (HOST nodes; no barriers) --------
__global__ void k_agg2(const int* __restrict__ hidx, const float* __restrict__ b2) {
    int hi = blockIdx.x;
    int t = threadIdx.x;       // 64
    int node = __ldg(&hidx[hi]);
    float m = d_xw2[(size_t)node * H2 + t];
    int e0 = d_off[node], e1 = d_off[node + 1];
    int e = e0;
    for (; e + 8 <= e1; e += 8) {
        int s0 = __ldg(&d_csr[e]);
        int s1 = __ldg(&d_csr[e + 1]);
        int s2 = __ldg(&d_csr[e + 2]);
        int s3 = __ldg(&d_csr[e + 3]);
        int s4 = __ldg(&d_csr[e + 4]);
        int s5 = __ldg(&d_csr[e + 5]);
        int s6 = __ldg(&d_csr[e + 6]);
        int s7 = __ldg(&d_csr[e + 7]);
        float v0 = __ldg(&d_xw2[(size_t)s0 * H2 + t]);
        float v1 = __ldg(&d_xw2[(size_t)s1 * H2 + t]);
        float v2 = __ldg(&d_xw2[(size_t)s2 * H2 + t]);
        float v3 = __ldg(&d_xw2[(size_t)s3 * H2 + t]);
        float v4 = __ldg(&d_xw2[(size_t)s4 * H2 + t]);
        float v5 = __ldg(&d_xw2[(size_t)s5 * H2 + t]);
        float v6 = __ldg(&d_xw2[(size_t)s6 * H2 + t]);
        float v7 = __ldg(&d_xw2[(size_t)s7 * H2 + t]);
        float m0 = fmaxf(fmaxf(v0, v1), fmaxf(v2, v3));
        float m1 = fmaxf(fmaxf(v4, v5), fmaxf(v6, v7));
        m = fmaxf(m, fmaxf(m0, m1));
    }
    for (; e < e1; e++)
        m = fmaxf(m, __ldg(&d_xw2[(size_t)__ldg(&d_csr[e]) * H2 + t]));
    d_x2h[(size_t)hi * H2 + t] = fmaxf(d_dinv[node] * m + b2[t], 0.f);
}

// ---------------- attn phase A: grid (BB, 2). y=0 → logits, y=1 → feats ----
template <int F, int H>
__global__ void k_attnA(const float* __restrict__ v, const int* __restrict__ hidx,
                        const float* __restrict__ aW, const float* __restrict__ ab,
                        const float* __restrict__ fW, const float* __restrict__ fb) {
    int b = blockIdx.x;
    int which = blockIdx.y;
    const float* W  = which ? fW : aW;
    const float* bb = which ? fb : ab;
    float* outg     = which ? d_fs : d_ls;
    int t = threadIdx.x;  // 256

    __shared__ float vsT[F][14];
    for (int i = t; i < NHOST * F; i += 256) {
        int h = i / F, f = i % F;
        int row = hidx ? hidx[b * NHOST + h] : (b * NHOST + h);
        vsT[f][h] = v[(size_t)row * F + f];
    }
    for (int f = t; f < F; f += 256) vsT[f][13] = 0.f;
    __syncthreads();

    if (t < H) {
        u64 acc[7];
#pragma unroll
        for (int p = 0; p < 7; p++) acc[p] = 0ull;
        for (int f = 0; f < F; f += 4) {
            float wv[4];
#pragma unroll
            for (int j = 0; j < 4; j++) wv[j] = __ldg(&W[(f + j) * H + t]);
#pragma unroll
            for (int j = 0; j < 4; j++) {
                u64 w2;
                asm("mov.b64 %0, {%1, %1};" : "=l"(w2) : "f"(wv[j]));
#pragma unroll
                for (int p = 0; p < 7; p++) {
                    u64 xv = *reinterpret_cast<const u64*>(&vsT[f + j][2 * p]);
                    asm("fma.rn.f32x2 %0, %1, %2, %0;" : "+l"(acc[p]) : "l"(xv), "l"(w2));
                }
            }
        }
        float bv = __ldg(&bb[t]);
        size_t gbase = (size_t)b * NHOST * H;
#pragma unroll
        for (int p = 0; p < 7; p++) {
            float lo, hi;
            asm("mov.b64 {%0, %1}, %2;" : "=f"(lo), "=f"(hi) : "l"(acc[p]));
            outg[gbase + (2 * p) * H + t] = lo + bv;
            if (2 * p + 1 < NHOST)
                outg[gbase + (2 * p + 1) * H + t] = hi + bv;
        }
    }
}

// ---------------- attn phases B–D: softmax + weighted sum + g-update -------
template <int H>
__global__ void k_attnB(const float* __restrict__ gW, const float* __restrict__ gb) {
    int b = blockIdx.x;
    int t = threadIdx.x;           // 256
    int lane = t & 31, w = t >> 5; // 8 warps

    __shared__ float ls[NHOST * H];
    __shared__ float fs[NHOST * H];
    __shared__ float mx[NHOST], rinv[NHOST];
    __shared__ float outs[H];
    __shared__ float gs[H1];

    size_t gbase = (size_t)b * NHOST * H;
    for (int i = t; i < NHOST * H; i += 256) {
        ls[i] = d_ls[gbase + i];
        fs[i] = d_fs[gbase + i];
    }
    gs[t] = d_g[(size_t)b * H1 + t];
    __syncthreads();

    for (int h = w; h < NHOST; h += 8) {
        float m = -1e30f;
        for (int j = lane; j < H; j += 32) m = fmaxf(m, ls[h * H + j]);
#pragma unroll
        for (int d = 16; d > 0; d >>= 1) m = fmaxf(m, __shfl_xor_sync(0xffffffffu, m, d));
        if (lane == 0) mx[h] = m;
    }
    __syncthreads();
    for (int i = t; i < NHOST * H; i += 256) ls[i] = expf(ls[i] - mx[i / H]);
    __syncthreads();
    for (int h = w; h < NHOST; h += 8) {
        float s = 0.f;
        for (int j = lane; j < H; j += 32) s += ls[h * H + j];
#pragma unroll
        for (int d = 16; d > 0; d >>= 1) s += __shfl_xor_sync(0xffffffffu, s, d);
        if (lane == 0) rinv[h] = 1.0f / s;
    }
    __syncthreads();

    if (t < H) {
        float o = 0.f;
#pragma unroll
        for (int h = 0; h < NHOST; h++)
            o += ls[h * H + t] * rinv[h] * fs[h * H + t];
        outs[t] = o;
    }
    __syncthreads();

    float a0 = __ldg(&gb[t]), a1 = 0.f, a2 = 0.f, a3 = 0.f;
    for (int k = 0; k < H; k += 4) {
        a0 += outs[k]     * __ldg(&gW[(k)     * H1 + t]);
        a1 += outs[k + 1] * __ldg(&gW[(k + 1) * H1 + t]);
        a2 += outs[k + 2] * __ldg(&gW[(k + 2) * H1 + t]);
        a3 += outs[k + 3] * __ldg(&gW[(k + 3) * H1 + t]);
    }
    for (int k = 0; k < H1; k += 4) {
        a0 += gs[k]     * __ldg(&gW[(H + k)     * H1 + t]);
        a1 += gs[k + 1] * __ldg(&gW[(H + k + 1) * H1 + t]);
        a2 += gs[k + 2] * __ldg(&gW[(H + k + 2) * H1 + t]);
        a3 += gs[k + 3] * __ldg(&gW[(H + k + 3) * H1 + t]);
    }
    d_g[(size_t)b * H1 + t] = gs[t] + (a0 + a1) + (a2 + a3);
}

// ---------------- final head: relu(g@o1W+o1b)@o2W + o2b -------------------
__global__ void k_head(const float* __restrict__ o1W, const float* __restrict__ o1b,
                       const float* __restrict__ o2W, const float* __restrict__ o2b,
                       float* __restrict__ out) {
    int b = blockIdx.x;
    int t = threadIdx.x; // 64
    __shared__ float gs[H1];
    for (int i = t; i < H1; i += 64) gs[i] = d_g[(size_t)b * H1 + i];
    __syncthreads();
    float a0 = o1b[t], a1 = 0.f, a2 = 0.f, a3 = 0.f;
    for (int k = 0; k < H1; k += 4) {
        a0 += gs[k]     * __ldg(&o1W[(k)     * H2 + t]);
        a1 += gs[k + 1] * __ldg(&o1W[(k + 1) * H2 + t]);
        a2 += gs[k + 2] * __ldg(&o1W[(k + 2) * H2 + t]);
        a3 += gs[k + 3] * __ldg(&o1W[(k + 3) * H2 + t]);
    }
    float acc = (a0 + a1) + (a2 + a3);
    float v = fmaxf(acc, 0.f) * __ldg(&o2W[t]);
    __shared__ float rs[64];
    rs[t] = v;
    __syncthreads();
    if (t < 32) {
        float s = rs[t] + rs[t + 32];
#pragma unroll
        for (int d = 16; d > 0; d >>= 1) s += __shfl_down_sync(0xffffffffu, s, d);
        if (t == 0) out[b] = s + o2b[0];
    }
}

// ---------------- launch ---------------------------------------------------
extern "C" void kernel_launch(void* const* d_in, const int* in_sizes, int n_in,
                              void* d_out, int out_size) {
    const float* x       = (const float*)d_in[0];
    const int*   ei      = (const int*)d_in[1];
    const int*   hostidx = (const int*)d_in[2];
    const float* W1 = (const float*)d_in[3];
    const float* b1 = (const float*)d_in[4];
    const float* W2 = (const float*)d_in[5];
    const float* b2 = (const float*)d_in[6];
    const float* a0W = (const float*)d_in[7];  const float* a0b = (const float*)d_in[8];
    const float* f0W = (const float*)d_in[9];  const float* f0b = (const float*)d_in[10];
    const float* g0W = (const float*)d_in[11]; const float* g0b = (const float*)d_in[12];
    const float* a1W = (const float*)d_in[13]; const float* a1b = (const float*)d_in[14];
    const float* f1W = (const float*)d_in[15]; const float* f1b = (const float*)d_in[16];
    const float* g1W = (const float*)d_in[17]; const float* g1b = (const float*)d_in[18];
    const float* a2W = (const float*)d_in[19]; const float* a2b = (const float*)d_in[20];
    const float* f2W = (const float*)d_in[21]; const float* f2b = (const float*)d_in[22];
    const float* g2W = (const float*)d_in[23]; const float* g2b = (const float*)d_in[24];
    const float* o1W = (const float*)d_in[25]; const float* o1b = (const float*)d_in[26];
    const float* o2W = (const float*)d_in[27]; const float* o2b = (const float*)d_in[28];
    float* out = (float*)d_out;

    const int* src = ei;
    const int* dst = ei + EE;

    float* x1_ptr;  cudaGetSymbolAddress((void**)&x1_ptr,  d_x1);
    float* x2h_ptr; cudaGetSymbolAddress((void**)&x2h_ptr, d_x2h);

    dim3 gA(BB, 2);

    k_zero<<<ZN / 256, 256>>>();                               // 1
    k_count_mh<<<(EE + 255) / 256, 256>>>(dst, hostidx);       // 2
    k_scan1<<<NB, 256>>>();                                    // 3
    // stage-0 attn phase A — slot 4 → profiled (sentinel)
    k_attnA<IN_F, H1><<<gA, 256>>>(x, hostidx, a0W, a0b, f0W, f0b);   // 4
    k_attnB<H1><<<BB, 256>>>(g0W, g0b);                        // 5
    k_scan2<<<1, 256>>>();                                     // 6
    k_scan3<<<NB, 256>>>();                                    // 7
    k_gemm1<<<NN / G1R, 256>>>(x, W1);                         // 8
    k_fill_me<<<(EE + 255) / 256, 256>>>(src, dst);            // 9
    k_mklist<<<NN / 256, 256>>>();                             // 10

    // layer 1
    k_agg1<<<NN, 256>>>(b1);                                   // 11 (r12 form)
    k_attnA<H1, H1><<<gA, 256>>>(x1_ptr, hostidx, a1W, a1b, f1W, f1b); // 12
    k_attnB<H1><<<BB, 256>>>(g1W, g1b);                        // 13

    // layer 2
    k_gemm2<<<(NN + G2R - 1) / G2R, 256>>>(W2);                // 14
    k_agg2<<<BB * NHOST, 64>>>(hostidx, b2);                   // 15
    k_attnA<H2, H2><<<gA, 256>>>(x2h_ptr, (const int*)nullptr, a2W, a2b, f2W, f2b); // 16
    k_attnB<H2><<<BB, 256>>>(g2W, g2b);                        // 17

    // head
    k_head<<<BB, 64>>>(o1W, o1b, o2W, o2b, out);               // 18
}

// round 15
// speedup vs baseline: 1.1275x; 1.1275x over previous
#include <cuda_runtime.h>
#include <math.h>

#define NN 51200      // nodes
#define EE 409600     // edges (without self loops)
#define BB 256        // batch
#define NHOST 13
#define IN_F 64
#define H1 256
#define H2 64
#define ZN 65536      // max(NN, BB*H1) — elements to zero
#define NB 200        // NN / 256 scan blocks

typedef unsigned long long u64;

// ---------------- scratch (static device globals; no runtime alloc) -------
__device__ int   d_cnt[NN];
__device__ int   d_off[NN + 1];
__device__ int   d_cur[NN];
__device__ int   d_csr[EE];
__device__ int   d_flag[NN];
__device__ int   d_ishost[NN];
__device__ int   d_list[NN];
__device__ int   d_nf;
__device__ int   d_bsum[NB];
__device__ int   d_bbase[NB];
__device__ float d_dinv[NN];
__device__ float d_xw[(size_t)NN * H1];    // dinv * (x @ W1)
__device__ float d_x1[(size_t)NN * H1];    // relu(agg1 + b1) on frontier rows
__device__ float d_xw2[(size_t)NN * H2];   // dinv * (x1 @ W2), frontier rows only
__device__ float d_x2h[(size_t)BB * NHOST * H2];
__device__ float d_g[(size_t)BB * H1];     // global state

// ---------------- zero ------------------------------------------------------
__global__ void k_zero() {
    int i = blockIdx.x * blockDim.x + threadIdx.x;
    if (i < NN) { d_cnt[i] = 0; d_flag[i] = 0; d_ishost[i] = 0; }
    if (i < BB * H1) d_g[i] = 0.f;
    if (i == 0) d_nf = 0;
}

__global__ void k_count_mh(const int* __restrict__ dst, const int* __restrict__ hidx) {
    int e = blockIdx.x * blockDim.x + threadIdx.x;
    if (e < EE) atomicAdd(&d_cnt[dst[e]], 1);
    if (e < BB * NHOST) {
        int n = hidx[e];
        d_ishost[n] = 1;
        d_flag[n] = 1;
    }
}

// dinv only needs counts — runs right after count so gemm1 can go early
__global__ void k_dinv() {
    int i = blockIdx.x * blockDim.x + threadIdx.x;
    if (i < NN) d_dinv[i] = rsqrtf((float)(d_cnt[i] + 1));  // +1 self loop
}

// ---------------- parallel 3-phase scan -------------------------------------
__global__ void k_scan1() {
    __shared__ int sh[256];
    int t = threadIdx.x;
    sh[t] = d_cnt[blockIdx.x * 256 + t];
    __syncthreads();
#pragma unroll
    for (int d = 128; d > 0; d >>= 1) {
        if (t < d) sh[t] += sh[t + d];
        __syncthreads();
    }
    if (t == 0) d_bsum[blockIdx.x] = sh[0];
}

__global__ void k_scan2() {
    __shared__ int sh[256];
    int t = threadIdx.x;
    int v = (t < NB) ? d_bsum[t] : 0;
    sh[t] = v;
    __syncthreads();
#pragma unroll
    for (int d = 1; d < 256; d <<= 1) {
        int x = sh[t];
        int add = (t >= d) ? sh[t - d] : 0;
        __syncthreads();
        sh[t] = x + add;
        __syncthreads();
    }
    if (t < NB) d_bbase[t] = sh[t] - v;  // exclusive
}

__global__ void k_scan3() {
    __shared__ int sh[256];
    int t = threadIdx.x;
    int i = blockIdx.x * 256 + t;
    int c = d_cnt[i];
    sh[t] = c;
    __syncthreads();
#pragma unroll
    for (int d = 1; d < 256; d <<= 1) {
        int x = sh[t];
        int add = (t >= d) ? sh[t - d] : 0;
        __syncthreads();
        sh[t] = x + add;
        __syncthreads();
    }
    int off = d_bbase[blockIdx.x] + sh[t] - c;
    d_off[i] = off;
    d_cur[i] = off;
    if (i == 0) d_off[NN] = EE;
}

__global__ void k_fill_me(const int* __restrict__ src, const int* __restrict__ dst) {
    int e = blockIdx.x * blockDim.x + threadIdx.x;
    if (e < EE) {
        int d = dst[e];
        int s = src[e];
        int p = atomicAdd(&d_cur[d], 1);
        d_csr[p] = s;
        if (d_ishost[d]) d_flag[s] = 1;
    }
}

__global__ void k_mklist() {
    int i = blockIdx.x * blockDim.x + threadIdx.x;
    if (i < NN && d_flag[i]) {
        int p = atomicAdd(&d_nf, 1);
        d_list[p] = i;
    }
}

// ---------------- GEMM1: xw = dinv * (x @ W1)  [51200,64]x[64,256] ---------
#define G1R 32
__global__ void __launch_bounds__(256, 4) k_gemm1(
        const float* __restrict__ x, const float* __restrict__ W1) {
    __shared__ float xs[IN_F][G1R + 2];
    int r0 = blockIdx.x * G1R;
    int t = threadIdx.x; // 256
    int rg = t >> 6;
    int cg = t & 63;
    for (int i = t; i < G1R * IN_F; i += 256) {
        int r = i >> 6, k = i & 63;
        xs[k][r] = x[(size_t)(r0 + r) * IN_F + k];
    }
    __syncthreads();
    u64 acc[4][4];
#pragma unroll
    for (int p = 0; p < 4; p++)
#pragma unroll
        for (int c = 0; c < 4; c++) acc[p][c] = 0ull;
    for (int k = 0; k < IN_F; k++) {
        float4 w4 = *reinterpret_cast<const float4*>(&W1[k * H1 + cg * 4]);
        u64 wd[4];
        asm("mov.b64 %0, {%1, %1};" : "=l"(wd[0]) : "f"(w4.x));
        asm("mov.b64 %0, {%1, %1};" : "=l"(wd[1]) : "f"(w4.y));
        asm("mov.b64 %0, {%1, %1};" : "=l"(wd[2]) : "f"(w4.z));
        asm("mov.b64 %0, {%1, %1};" : "=l"(wd[3]) : "f"(w4.w));
        u64 xp[4];
#pragma unroll
        for (int p = 0; p < 4; p++)
            xp[p] = *reinterpret_cast<const u64*>(&xs[k][rg * 8 + 2 * p]);
#pragma unroll
        for (int p = 0; p < 4; p++)
#pragma unroll
            for (int c = 0; c < 4; c++)
                asm("fma.rn.f32x2 %0, %1, %2, %0;" : "+l"(acc[p][c]) : "l"(xp[p]), "l"(wd[c]));
    }
#pragma unroll
    for (int p = 0; p < 4; p++) {
        float lo[4], hi[4];
#pragma unroll
        for (int c = 0; c < 4; c++)
            asm("mov.b64 {%0, %1}, %2;" : "=f"(lo[c]), "=f"(hi[c]) : "l"(acc[p][c]));
        int ra = r0 + rg * 8 + 2 * p;
        float da = d_dinv[ra], db = d_dinv[ra + 1];
        float4 oa = make_float4(da * lo[0], da * lo[1], da * lo[2], da * lo[3]);
        float4 ob = make_float4(db * hi[0], db * hi[1], db * hi[2], db * hi[3]);
        *reinterpret_cast<float4*>(&d_xw[(size_t)ra * H1 + cg * 4])       = oa;
        *reinterpret_cast<float4*>(&d_xw[(size_t)(ra + 1) * H1 + cg * 4]) = ob;
    }
}

// ---------------- layer-1 max aggregation (r12 proven form) ----------------
__global__ void k_agg1(const float* __restrict__ b1) {
    int bi = blockIdx.x;
    if (bi >= d_nf) return;
    int i = d_list[bi];
    int t = threadIdx.x; // 256
    float m = d_xw[(size_t)i * H1 + t];
    int e0 = d_off[i], e1 = d_off[i + 1];
    int e = e0;
    for (; e + 8 <= e1; e += 8) {
        int s0 = __ldg(&d_csr[e]);
        int s1 = __ldg(&d_csr[e + 1]);
        int s2 = __ldg(&d_csr[e + 2]);
        int s3 = __ldg(&d_csr[e + 3]);
        int s4 = __ldg(&d_csr[e + 4]);
        int s5 = __ldg(&d_csr[e + 5]);
        int s6 = __ldg(&d_csr[e + 6]);
        int s7 = __ldg(&d_csr[e + 7]);
        float v0 = __ldg(&d_xw[(size_t)s0 * H1 + t]);
        float v1 = __ldg(&d_xw[(size_t)s1 * H1 + t]);
        float v2 = __ldg(&d_xw[(size_t)s2 * H1 + t]);
        float v3 = __ldg(&d_xw[(size_t)s3 * H1 + t]);
        float v4 = __ldg(&d_xw[(size_t)s4 * H1 + t]);
        float v5 = __ldg(&d_xw[(size_t)s5 * H1 + t]);
        float v6 = __ldg(&d_xw[(size_t)s6 * H1 + t]);
        float v7 = __ldg(&d_xw[(size_t)s7 * H1 + t]);
        float m0 = fmaxf(fmaxf(v0, v1), fmaxf(v2, v3));
        float m1 = fmaxf(fmaxf(v4, v5), fmaxf(v6, v7));
        m = fmaxf(m, fmaxf(m0, m1));
    }
    for (; e < e1; e++)
        m = fmaxf(m, __ldg(&d_xw[(size_t)__ldg(&d_csr[e]) * H1 + t]));
    d_x1[(size_t)i * H1 + t] = fmaxf(d_dinv[i] * m + b1[t], 0.f);
}

// ---------------- GEMM2 on frontier rows: xw2 = dinv * (x1 @ W2) -----------
#define G2R 128
__global__ void __launch_bounds__(256, 4) k_gemm2(const float* __restrict__ W2) {
    int r0 = blockIdx.x * G2R;
    int nf = d_nf;
    if (r0 >= nf) return;
    __shared__ float xs[64][G2R + 2];
    __shared__ int rows[G2R];
    int t = threadIdx.x;      // 256
    int rg = t >> 4;
    int cg = t & 15;
    if (t < G2R) rows[t] = d_list[min(r0 + t, nf - 1)];
    __syncthreads();
    u64 acc[4][4];
#pragma unroll
    for (int p = 0; p < 4; p++)
#pragma unroll
        for (int c = 0; c < 4; c++) acc[p][c] = 0ull;
    for (int kc = 0; kc < H1; kc += 64) {
        __syncthreads();
        for (int i = t; i < G2R * 64; i += 256) {
            int r = i >> 6, k = i & 63;
            xs[k][r] = d_x1[(size_t)rows[r] * H1 + kc + k];
        }
        __syncthreads();
        for (int k = 0; k < 64; k++) {
            float4 w4 = *reinterpret_cast<const float4*>(&W2[(kc + k) * H2 + cg * 4]);
            u64 wd[4];
            asm("mov.b64 %0, {%1, %1};" : "=l"(wd[0]) : "f"(w4.x));
            asm("mov.b64 %0, {%1, %1};" : "=l"(wd[1]) : "f"(w4.y));
            asm("mov.b64 %0, {%1, %1};" : "=l"(wd[2]) : "f"(w4.z));
            asm("mov.b64 %0, {%1, %1};" : "=l"(wd[3]) : "f"(w4.w));
            u64 xp[4];
#pragma unroll
            for (int p = 0; p < 4; p++)
                xp[p] = *reinterpret_cast<const u64*>(&xs[k][rg * 8 + 2 * p]);
#pragma unroll
            for (int p = 0; p < 4; p++)
#pragma unroll
                for (int c = 0; c < 4; c++)
                    asm("fma.rn.f32x2 %0, %1, %2, %0;" : "+l"(acc[p][c]) : "l"(xp[p]), "l"(wd[c]));
        }
    }
#pragma unroll
    for (int p = 0; p < 4; p++) {
        float lo[4], hi[4];
#pragma unroll
        for (int c = 0; c < 4; c++)
            asm("mov.b64 {%0, %1}, %2;" : "=f"(lo[c]), "=f"(hi[c]) : "l"(acc[p][c]));
        int rla = rg * 8 + 2 * p;
        int ga = rows[rla], gb2 = rows[rla + 1];
        float da = d_dinv[ga], db = d_dinv[gb2];
        float4 oa = make_float4(da * lo[0], da * lo[1], da * lo[2], da * lo[3]);
        float4 ob = make_float4(db * hi[0], db * hi[1], db * hi[2], db * hi[3]);
        *reinterpret_cast<float4*>(&d_xw2[(size_t)ga * H2 + cg * 4])  = oa;
        *reinterpret_cast<float4*>(&d_xw2[(size_t)gb2 * H2 + cg * 4]) = ob;
    }
}

// ---------------- layer-2 max aggregation (HOST nodes; no barriers) --------
__global__ void k_agg2(const int* __restrict__ hidx, const float* __restrict__ b2) {
    int hi = blockIdx.x;
    int t = threadIdx.x;       // 64
    int node = __ldg(&hidx[hi]);
    float m = d_xw2[(size_t)node * H2 + t];
    int e0 = d_off[node], e1 = d_off[node + 1];
    int e = e0;
    for (; e + 8 <= e1; e += 8) {
        int s0 = __ldg(&d_csr[e]);
        int s1 = __ldg(&d_csr[e + 1]);
        int s2 = __ldg(&d_csr[e + 2]);
        int s3 = __ldg(&d_csr[e + 3]);
        int s4 = __ldg(&d_csr[e + 4]);
        int s5 = __ldg(&d_csr[e + 5]);
        int s6 = __ldg(&d_csr[e + 6]);
        int s7 = __ldg(&d_csr[e + 7]);
        float v0 = __ldg(&d_xw2[(size_t)s0 * H2 + t]);
        float v1 = __ldg(&d_xw2[(size_t)s1 * H2 + t]);
        float v2 = __ldg(&d_xw2[(size_t)s2 * H2 + t]);
        float v3 = __ldg(&d_xw2[(size_t)s3 * H2 + t]);
        float v4 = __ldg(&d_xw2[(size_t)s4 * H2 + t]);
        float v5 = __ldg(&d_xw2[(size_t)s5 * H2 + t]);
        float v6 = __ldg(&d_xw2[(size_t)s6 * H2 + t]);
        float v7 = __ldg(&d_xw2[(size_t)s7 * H2 + t]);
        float m0 = fmaxf(fmaxf(v0, v1), fmaxf(v2, v3));
        float m1 = fmaxf(fmaxf(v4, v5), fmaxf(v6, v7));
        m = fmaxf(m, fmaxf(m0, m1));
    }
    for (; e < e1; e++)
        m = fmaxf(m, __ldg(&d_xw2[(size_t)__ldg(&d_csr[e]) * H2 + t]));
    d_x2h[(size_t)hi * H2 + t] = fmaxf(d_dinv[node] * m + b2[t], 0.f);
}

// ---------------- fused self attention (r12 proven form) -------------------
template <int F, int H>
__global__ void k_attn(const float* __restrict__ v, const int* __restrict__ hidx,
                       const float* __restrict__ aW, const float* __restrict__ ab,
                       const float* __restrict__ fW, const float* __restrict__ fb,
                       const float* __restrict__ gW, const float* __restrict__ gb) {
    int b = blockIdx.x;
    int t = threadIdx.x;           // 256
    int lane = t & 31, w = t >> 5; // 8 warps

    __shared__ float vsT[F][14];
    __shared__ float ls[NHOST * H];
    __shared__ float fs[NHOST * H];
    __shared__ float mx[NHOST], rinv[NHOST];
    __shared__ float outs[H];
    __shared__ float gs[H1];

    for (int i = t; i < NHOST * F; i += 256) {
        int h = i / F, f = i % F;
        int row = hidx ? hidx[b * NHOST + h] : (b * NHOST + h);
        vsT[f][h] = v[(size_t)row * F + f];
    }
    for (int f = t; f < F; f += 256) vsT[f][13] = 0.f;
    gs[t] = d_g[(size_t)b * H1 + t];
    __syncthreads();

    if (t < H) {
        u64 aLp[7], fVp[7];
#pragma unroll
        for (int p = 0; p < 7; p++) { aLp[p] = 0ull; fVp[p] = 0ull; }
        for (int f = 0; f < F; f += 4) {
            float wa[4], wf[4];
#pragma unroll
            for (int j = 0; j < 4; j++) {
                wa[j] = __ldg(&aW[(f + j) * H + t]);
                wf[j] = __ldg(&fW[(f + j) * H + t]);
            }
#pragma unroll
            for (int j = 0; j < 4; j++) {
                u64 wa2, wf2;
                asm("mov.b64 %0, {%1, %1};" : "=l"(wa2) : "f"(wa[j]));
                asm("mov.b64 %0, {%1, %1};" : "=l"(wf2) : "f"(wf[j]));
#pragma unroll
                for (int p = 0; p < 7; p++) {
                    u64 xv = *reinterpret_cast<const u64*>(&vsT[f + j][2 * p]);
                    asm("fma.rn.f32x2 %0, %1, %2, %0;" : "+l"(aLp[p]) : "l"(xv), "l"(wa2));
                    asm("fma.rn.f32x2 %0, %1, %2, %0;" : "+l"(fVp[p]) : "l"(xv), "l"(wf2));
                }
            }
        }
        float abv = __ldg(&ab[t]), fbv = __ldg(&fb[t]);
#pragma unroll
        for (int p = 0; p < 7; p++) {
            float alo, ahi, flo, fhi;
            asm("mov.b64 {%0, %1}, %2;" : "=f"(alo), "=f"(ahi) : "l"(aLp[p]));
            asm("mov.b64 {%0, %1}, %2;" : "=f"(flo), "=f"(fhi) : "l"(fVp[p]));
            ls[(2 * p) * H + t] = alo + abv;
            fs[(2 * p) * H + t] = flo + fbv;
            if (2 * p + 1 < NHOST) {
                ls[(2 * p + 1) * H + t] = ahi + abv;
                fs[(2 * p + 1) * H + t] = fhi + fbv;
            }
        }
    }
    __syncthreads();

    for (int h = w; h < NHOST; h += 8) {
        float m = -1e30f;
        for (int j = lane; j < H; j += 32) m = fmaxf(m, ls[h * H + j]);
#pragma unroll
        for (int d = 16; d > 0; d >>= 1) m = fmaxf(m, __shfl_xor_sync(0xffffffffu, m, d));
        if (lane == 0) mx[h] = m;
    }
    __syncthreads();
    for (int i = t; i < NHOST * H; i += 256) ls[i] = expf(ls[i] - mx[i / H]);
    __syncthreads();
    for (int h = w; h < NHOST; h += 8) {
        float s = 0.f;
        for (int j = lane; j < H; j += 32) s += ls[h * H + j];
#pragma unroll
        for (int d = 16; d > 0; d >>= 1) s += __shfl_xor_sync(0xffffffffu, s, d);
        if (lane == 0) rinv[h] = 1.0f / s;
    }
    __syncthreads();

    if (t < H) {
        float o = 0.f;
#pragma unroll
        for (int h = 0; h < NHOST; h++)
            o += ls[h * H + t] * rinv[h] * fs[h * H + t];
        outs[t] = o;
    }
    __syncthreads();

    float a0 = __ldg(&gb[t]), a1 = 0.f, a2 = 0.f, a3 = 0.f;
    for (int k = 0; k < H; k += 4) {
        a0 += outs[k]     * __ldg(&gW[(k)     * H1 + t]);
        a1 += outs[k + 1] * __ldg(&gW[(k + 1) * H1 + t]);
        a2 += outs[k + 2] * __ldg(&gW[(k + 2) * H1 + t]);
        a3 += outs[k + 3] * __ldg(&gW[(k + 3) * H1 + t]);
    }
    for (int k = 0; k < H1; k += 4) {
        a0 += gs[k]     * __ldg(&gW[(H + k)     * H1 + t]);
        a1 += gs[k + 1] * __ldg(&gW[(H + k + 1) * H1 + t]);
        a2 += gs[k + 2] * __ldg(&gW[(H + k + 2) * H1 + t]);
        a3 += gs[k + 3] * __ldg(&gW[(H + k + 3) * H1 + t]);
    }
    d_g[(size_t)b * H1 + t] = gs[t] + (a0 + a1) + (a2 + a3);
}

// ---------------- stage-2 attention + head fused (g never leaves smem) -----
__global__ void k_attn2h(const float* __restrict__ v,
                         const float* __restrict__ aW, const float* __restrict__ ab,
                         const float* __restrict__ fW, const float* __restrict__ fb,
                         const float* __restrict__ gW, const float* __restrict__ gb,
                         const float* __restrict__ o1W, const float* __restrict__ o1b,
                         const float* __restrict__ o2W, const float* __restrict__ o2b,
                         float* __restrict__ out) {
    constexpr int F = H2, H = H2;
    int b = blockIdx.x;
    int t = threadIdx.x;           // 256
    int lane = t & 31, w = t >> 5; // 8 warps

    __shared__ float vsT[F][14];
    __shared__ float ls[NHOST * H];
    __shared__ float fs[NHOST * H];
    __shared__ float mx[NHOST], rinv[NHOST];
    __shared__ float outs[H];
    __shared__ float gs[H1];
    __shared__ float gn[H1];
    __shared__ float rs[64];

    for (int i = t; i < NHOST * F; i += 256) {
        int h = i / F, f = i % F;
        vsT[f][h] = v[(size_t)(b * NHOST + h) * F + f];
    }
    for (int f = t; f < F; f += 256) vsT[f][13] = 0.f;
    gs[t] = d_g[(size_t)b * H1 + t];
    __syncthreads();

    if (t < H) {
        u64 aLp[7], fVp[7];
#pragma unroll
        for (int p = 0; p < 7; p++) { aLp[p] = 0ull; fVp[p] = 0ull; }
        for (int f = 0; f < F; f += 4) {
            float wa[4], wf[4];
#pragma unroll
            for (int j = 0; j < 4; j++) {
                wa[j] = __ldg(&aW[(f + j) * H + t]);
                wf[j] = __ldg(&fW[(f + j) * H + t]);
            }
#pragma unroll
            for (int j = 0; j < 4; j++) {
                u64 wa2, wf2;
                asm("mov.b64 %0, {%1, %1};" : "=l"(wa2) : "f"(wa[j]));
                asm("mov.b64 %0, {%1, %1};" : "=l"(wf2) : "f"(wf[j]));
#pragma unroll
                for (int p = 0; p < 7; p++) {
                    u64 xv = *reinterpret_cast<const u64*>(&vsT[f + j][2 * p]);
                    asm("fma.rn.f32x2 %0, %1, %2, %0;" : "+l"(aLp[p]) : "l"(xv), "l"(wa2));
                    asm("fma.rn.f32x2 %0, %1, %2, %0;" : "+l"(fVp[p]) : "l"(xv), "l"(wf2));
                }
            }
        }
        float abv = __ldg(&ab[t]), fbv = __ldg(&fb[t]);
#pragma unroll
        for (int p = 0; p < 7; p++) {
            float alo, ahi, flo, fhi;
            asm("mov.b64 {%0, %1}, %2;" : "=f"(alo), "=f"(ahi) : "l"(aLp[p]));
            asm("mov.b64 {%0, %1}, %2;" : "=f"(flo), "=f"(fhi) : "l"(fVp[p]));
            ls[(2 * p) * H + t] = alo + abv;
            fs[(2 * p) * H + t] = flo + fbv;
            if (2 * p + 1 < NHOST) {
                ls[(2 * p + 1) * H + t] = ahi + abv;
                fs[(2 * p + 1) * H + t] = fhi + fbv;
            }
        }
    }
    __syncthreads();

    for (int h = w; h < NHOST; h += 8) {
        float m = -1e30f;
        for (int j = lane; j < H; j += 32) m = fmaxf(m, ls[h * H + j]);
#pragma unroll
        for (int d = 16; d > 0; d >>= 1) m = fmaxf(m, __shfl_xor_sync(0xffffffffu, m, d));
        if (lane == 0) mx[h] = m;
    }
    __syncthreads();
    for (int i = t; i < NHOST * H; i += 256) ls[i] = expf(ls[i] - mx[i / H]);
    __syncthreads();
    for (int h = w; h < NHOST; h += 8) {
        float s = 0.f;
        for (int j = lane; j < H; j += 32) s += ls[h * H + j];
#pragma unroll
        for (int d = 16; d > 0; d >>= 1) s += __shfl_xor_sync(0xffffffffu, s, d);
        if (lane == 0) rinv[h] = 1.0f / s;
    }
    __syncthreads();

    if (t < H) {
        float o = 0.f;
#pragma unroll
        for (int h = 0; h < NHOST; h++)
            o += ls[h * H + t] * rinv[h] * fs[h * H + t];
        outs[t] = o;
    }
    __syncthreads();

    float a0 = __ldg(&gb[t]), a1 = 0.f, a2 = 0.f, a3 = 0.f;
    for (int k = 0; k < H; k += 4) {
        a0 += outs[k]     * __ldg(&gW[(k)     * H1 + t]);
        a1 += outs[k + 1] * __ldg(&gW[(k + 1) * H1 + t]);
        a2 += outs[k + 2] * __ldg(&gW[(k + 2) * H1 + t]);
        a3 += outs[k + 3] * __ldg(&gW[(k + 3) * H1 + t]);
    }
    for (int k = 0; k < H1; k += 4) {
        a0 += gs[k]     * __ldg(&gW[(H + k)     * H1 + t]);
        a1 += gs[k + 1] * __ldg(&gW[(H + k + 1) * H1 + t]);
        a2 += gs[k + 2] * __ldg(&gW[(H + k + 2) * H1 + t]);
        a3 += gs[k + 3] * __ldg(&gW[(H + k + 3) * H1 + t]);
    }
    gn[t] = gs[t] + (a0 + a1) + (a2 + a3);
    __syncthreads();

    // head: out[b] = relu(gn @ o1W + o1b) @ o2W + o2b
    if (t < 64) {
        float h0 = __ldg(&o1b[t]), h1 = 0.f, h2 = 0.f, h3 = 0.f;
        for (int k = 0; k < H1; k += 4) {
            h0 += gn[k]     * __ldg(&o1W[(k)     * H2 + t]);
            h1 += gn[k + 1] * __ldg(&o1W[(k + 1) * H2 + t]);
            h2 += gn[k + 2] * __ldg(&o1W[(k + 2) * H2 + t]);
            h3 += gn[k + 3] * __ldg(&o1W[(k + 3) * H2 + t]);
        }
        float acc = (h0 + h1) + (h2 + h3);
        rs[t] = fmaxf(acc, 0.f) * __ldg(&o2W[t]);
    }
    __syncthreads();
    if (t < 32) {
        float s = rs[t] + rs[t + 32];
#pragma unroll
        for (int d = 16; d > 0; d >>= 1) s += __shfl_down_sync(0xffffffffu, s, d);
        if (t == 0) out[b] = s + __ldg(&o2b[0]);
    }
}

// ---------------- launch ---------------------------------------------------
extern "C" void kernel_launch(void* const* d_in, const int* in_sizes, int n_in,
                              void* d_out, int out_size) {
    const float* x       = (const float*)d_in[0];
    const int*   ei      = (const int*)d_in[1];
    const int*   hostidx = (const int*)d_in[2];
    const float* W1 = (const float*)d_in[3];
    const float* b1 = (const float*)d_in[4];
    const float* W2 = (const float*)d_in[5];
    const float* b2 = (const float*)d_in[6];
    const float* a0W = (const float*)d_in[7];  const float* a0b = (const float*)d_in[8];
    const float* f0W = (const float*)d_in[9];  const float* f0b = (const float*)d_in[10];
    const float* g0W = (const float*)d_in[11]; const float* g0b = (const float*)d_in[12];
    const float* a1W = (const float*)d_in[13]; const float* a1b = (const float*)d_in[14];
    const float* f1W = (const float*)d_in[15]; const float* f1b = (const float*)d_in[16];
    const float* g1W = (const float*)d_in[17]; const float* g1b = (const float*)d_in[18];
    const float* a2W = (const float*)d_in[19]; const float* a2b = (const float*)d_in[20];
    const float* f2W = (const float*)d_in[21]; const float* f2b = (const float*)d_in[22];
    const float* g2W = (const float*)d_in[23]; const float* g2b = (const float*)d_in[24];
    const float* o1W = (const float*)d_in[25]; const float* o1b = (const float*)d_in[26];
    const float* o2W = (const float*)d_in[27]; const float* o2b = (const float*)d_in[28];
    float* out = (float*)d_out;

    const int* src = ei;
    const int* dst = ei + EE;

    float* x1_ptr;  cudaGetSymbolAddress((void**)&x1_ptr,  d_x1);
    float* x2h_ptr; cudaGetSymbolAddress((void**)&x2h_ptr, d_x2h);

    k_zero<<<ZN / 256, 256>>>();                               // 1
    k_count_mh<<<(EE + 255) / 256, 256>>>(dst, hostidx);       // 2
    k_dinv<<<NN / 256, 256>>>();                               // 3
    k_gemm1<<<NN / G1R, 256>>>(x, W1);                         // 4 ← profiled
    k_attn<IN_F, H1><<<BB, 256>>>(x, hostidx, a0W, a0b, f0W, f0b, g0W, g0b);    // 5
    k_scan1<<<NB, 256>>>();                                    // 6
    k_scan2<<<1, 256>>>();                                     // 7
    k_scan3<<<NB, 256>>>();                                    // 8
    k_fill_me<<<(EE + 255) / 256, 256>>>(src, dst);            // 9
    k_mklist<<<NN / 256, 256>>>();                             // 10

    // layer 1
    k_agg1<<<NN, 256>>>(b1);                                   // 11
    k_attn<H1, H1><<<BB, 256>>>(x1_ptr, hostidx, a1W, a1b, f1W, f1b, g1W, g1b); // 12

    // layer 2
    k_gemm2<<<(NN + G2R - 1) / G2R, 256>>>(W2);                // 13
    k_agg2<<<BB * NHOST, 64>>>(hostidx, b2);                   // 14
    k_attn2h<<<BB, 256>>>(x2h_ptr, a2W, a2b, f2W, f2b, g2W, g2b,
                          o1W, o1b, o2W, o2b, out);            // 15 (attn2 + head)
}

// round 16
// speedup vs baseline: 1.2064x; 1.0700x over previous
#include <cuda_runtime.h>
#include <math.h>

#define NN 51200      // nodes
#define EE 409600     // edges (without self loops)
#define BB 256        // batch
#define NHOST 13
#define IN_F 64
#define H1 256
#define H2 64
#define ZN 65536      // max(NN, BB*H1) — elements to zero
#define NB 200        // NN / 256 scan blocks

typedef unsigned long long u64;

// ---------------- scratch (static device globals; no runtime alloc) -------
__device__ int   d_cnt[NN];
__device__ int   d_off[NN + 1];
__device__ int   d_cur[NN];
__device__ int   d_csr[EE];
__device__ int   d_flag[NN];
__device__ int   d_ishost[NN];
__device__ int   d_list[NN];
__device__ int   d_nf;
__device__ int   d_bsum[NB];
__device__ int   d_bbase[NB];
__device__ float d_dinv[NN];
__device__ float d_xw[(size_t)NN * H1];    // dinv * (x @ W1)
__device__ float d_x1[(size_t)NN * H1];    // relu(agg1 + b1) on frontier rows
__device__ float d_xw2[(size_t)NN * H2];   // dinv * (x1 @ W2), frontier rows only
__device__ float d_x2h[(size_t)BB * NHOST * H2];
__device__ float d_g[(size_t)BB * H1];     // global state

// ---------------- zero ------------------------------------------------------
__global__ void k_zero() {
    int i = blockIdx.x * blockDim.x + threadIdx.x;
    if (i < NN) { d_cnt[i] = 0; d_flag[i] = 0; d_ishost[i] = 0; }
    if (i < BB * H1) d_g[i] = 0.f;
    if (i == 0) d_nf = 0;
}

__global__ void k_count_mh(const int* __restrict__ dst, const int* __restrict__ hidx) {
    int e = blockIdx.x * blockDim.x + threadIdx.x;
    if (e < EE) atomicAdd(&d_cnt[dst[e]], 1);
    if (e < BB * NHOST) {
        int n = hidx[e];
        d_ishost[n] = 1;
        d_flag[n] = 1;
    }
}

// dinv only needs counts
__global__ void k_dinv() {
    int i = blockIdx.x * blockDim.x + threadIdx.x;
    if (i < NN) d_dinv[i] = rsqrtf((float)(d_cnt[i] + 1));  // +1 self loop
}

// ---------------- parallel 3-phase scan -------------------------------------
__global__ void k_scan1() {
    __shared__ int sh[256];
    int t = threadIdx.x;
    sh[t] = d_cnt[blockIdx.x * 256 + t];
    __syncthreads();
#pragma unroll
    for (int d = 128; d > 0; d >>= 1) {
        if (t < d) sh[t] += sh[t + d];
        __syncthreads();
    }
    if (t == 0) d_bsum[blockIdx.x] = sh[0];
}

__global__ void k_scan2() {
    __shared__ int sh[256];
    int t = threadIdx.x;
    int v = (t < NB) ? d_bsum[t] : 0;
    sh[t] = v;
    __syncthreads();
#pragma unroll
    for (int d = 1; d < 256; d <<= 1) {
        int x = sh[t];
        int add = (t >= d) ? sh[t - d] : 0;
        __syncthreads();
        sh[t] = x + add;
        __syncthreads();
    }
    if (t < NB) d_bbase[t] = sh[t] - v;  // exclusive
}

__global__ void k_scan3() {
    __shared__ int sh[256];
    int t = threadIdx.x;
    int i = blockIdx.x * 256 + t;
    int c = d_cnt[i];
    sh[t] = c;
    __syncthreads();
#pragma unroll
    for (int d = 1; d < 256; d <<= 1) {
        int x = sh[t];
        int add = (t >= d) ? sh[t - d] : 0;
        __syncthreads();
        sh[t] = x + add;
        __syncthreads();
    }
    int off = d_bbase[blockIdx.x] + sh[t] - c;
    d_off[i] = off;
    d_cur[i] = off;
    if (i == 0) d_off[NN] = EE;
}

__global__ void k_fill_me(const int* __restrict__ src, const int* __restrict__ dst) {
    int e = blockIdx.x * blockDim.x + threadIdx.x;
    if (e < EE) {
        int d = dst[e];
        int s = src[e];
        int p = atomicAdd(&d_cur[d], 1);
        d_csr[p] = s;
        if (d_ishost[d]) d_flag[s] = 1;
    }
}

__global__ void k_mklist() {
    int i = blockIdx.x * blockDim.x + threadIdx.x;
    if (i < NN && d_flag[i]) {
        int p = atomicAdd(&d_nf, 1);
        d_list[p] = i;
    }
}

// ---------------- GEMM1: xw = dinv * (x @ W1)  [51200,64]x[64,256] ---------
#define G1R 32
__global__ void __launch_bounds__(256, 4) k_gemm1(
        const float* __restrict__ x, const float* __restrict__ W1) {
    __shared__ float xs[IN_F][G1R + 2];
    int r0 = blockIdx.x * G1R;
    int t = threadIdx.x; // 256
    int rg = t >> 6;
    int cg = t & 63;
    for (int i = t; i < G1R * IN_F; i += 256) {
        int r = i >> 6, k = i & 63;
        xs[k][r] = x[(size_t)(r0 + r) * IN_F + k];
    }
    __syncthreads();
    u64 acc[4][4];
#pragma unroll
    for (int p = 0; p < 4; p++)
#pragma unroll
        for (int c = 0; c < 4; c++) acc[p][c] = 0ull;
    for (int k = 0; k < IN_F; k++) {
        float4 w4 = *reinterpret_cast<const float4*>(&W1[k * H1 + cg * 4]);
        u64 wd[4];
        asm("mov.b64 %0, {%1, %1};" : "=l"(wd[0]) : "f"(w4.x));
        asm("mov.b64 %0, {%1, %1};" : "=l"(wd[1]) : "f"(w4.y));
        asm("mov.b64 %0, {%1, %1};" : "=l"(wd[2]) : "f"(w4.z));
        asm("mov.b64 %0, {%1, %1};" : "=l"(wd[3]) : "f"(w4.w));
        u64 xp[4];
#pragma unroll
        for (int p = 0; p < 4; p++)
            xp[p] = *reinterpret_cast<const u64*>(&xs[k][rg * 8 + 2 * p]);
#pragma unroll
        for (int p = 0; p < 4; p++)
#pragma unroll
            for (int c = 0; c < 4; c++)
                asm("fma.rn.f32x2 %0, %1, %2, %0;" : "+l"(acc[p][c]) : "l"(xp[p]), "l"(wd[c]));
    }
#pragma unroll
    for (int p = 0; p < 4; p++) {
        float lo[4], hi[4];
#pragma unroll
        for (int c = 0; c < 4; c++)
            asm("mov.b64 {%0, %1}, %2;" : "=f"(lo[c]), "=f"(hi[c]) : "l"(acc[p][c]));
        int ra = r0 + rg * 8 + 2 * p;
        float da = d_dinv[ra], db = d_dinv[ra + 1];
        float4 oa = make_float4(da * lo[0], da * lo[1], da * lo[2], da * lo[3]);
        float4 ob = make_float4(db * hi[0], db * hi[1], db * hi[2], db * hi[3]);
        *reinterpret_cast<float4*>(&d_xw[(size_t)ra * H1 + cg * 4])       = oa;
        *reinterpret_cast<float4*>(&d_xw[(size_t)(ra + 1) * H1 + cg * 4]) = ob;
    }
}

// ---------------- layer-1 max aggregation (r12 proven form) ----------------
__global__ void k_agg1(const float* __restrict__ b1) {
    int bi = blockIdx.x;
    if (bi >= d_nf) return;
    int i = d_list[bi];
    int t = threadIdx.x; // 256
    float m = d_xw[(size_t)i * H1 + t];
    int e0 = d_off[i], e1 = d_off[i + 1];
    int e = e0;
    for (; e + 8 <= e1; e += 8) {
        int s0 = __ldg(&d_csr[e]);
        int s1 = __ldg(&d_csr[e + 1]);
        int s2 = __ldg(&d_csr[e + 2]);
        int s3 = __ldg(&d_csr[e + 3]);
        int s4 = __ldg(&d_csr[e + 4]);
        int s5 = __ldg(&d_csr[e + 5]);
        int s6 = __ldg(&d_csr[e + 6]);
        int s7 = __ldg(&d_csr[e + 7]);
        float v0 = __ldg(&d_xw[(size_t)s0 * H1 + t]);
        float v1 = __ldg(&d_xw[(size_t)s1 * H1 + t]);
        float v2 = __ldg(&d_xw[(size_t)s2 * H1 + t]);
        float v3 = __ldg(&d_xw[(size_t)s3 * H1 + t]);
        float v4 = __ldg(&d_xw[(size_t)s4 * H1 + t]);
        float v5 = __ldg(&d_xw[(size_t)s5 * H1 + t]);
        float v6 = __ldg(&d_xw[(size_t)s6 * H1 + t]);
        float v7 = __ldg(&d_xw[(size_t)s7 * H1 + t]);
        float m0 = fmaxf(fmaxf(v0, v1), fmaxf(v2, v3));
        float m1 = fmaxf(fmaxf(v4, v5), fmaxf(v6, v7));
        m = fmaxf(m, fmaxf(m0, m1));
    }
    for (; e < e1; e++)
        m = fmaxf(m, __ldg(&d_xw[(size_t)__ldg(&d_csr[e]) * H1 + t]));
    d_x1[(size_t)i * H1 + t] = fmaxf(d_dinv[i] * m + b1[t], 0.f);
}

// ---------------- GEMM2 on frontier rows: xw2 = dinv * (x1 @ W2) -----------
#define G2R 128
__global__ void __launch_bounds__(256, 4) k_gemm2(const float* __restrict__ W2) {
    int r0 = blockIdx.x * G2R;
    int nf = d_nf;
    if (r0 >= nf) return;
    __shared__ float xs[64][G2R + 2];
    __shared__ int rows[G2R];
    int t = threadIdx.x;      // 256
    int rg = t >> 4;
    int cg = t & 15;
    if (t < G2R) rows[t] = d_list[min(r0 + t, nf - 1)];
    __syncthreads();
    u64 acc[4][4];
#pragma unroll
    for (int p = 0; p < 4; p++)
#pragma unroll
        for (int c = 0; c < 4; c++) acc[p][c] = 0ull;
    for (int kc = 0; kc < H1; kc += 64) {
        __syncthreads();
        for (int i = t; i < G2R * 64; i += 256) {
            int r = i >> 6, k = i & 63;
            xs[k][r] = d_x1[(size_t)rows[r] * H1 + kc + k];
        }
        __syncthreads();
        for (int k = 0; k < 64; k++) {
            float4 w4 = *reinterpret_cast<const float4*>(&W2[(kc + k) * H2 + cg * 4]);
            u64 wd[4];
            asm("mov.b64 %0, {%1, %1};" : "=l"(wd[0]) : "f"(w4.x));
            asm("mov.b64 %0, {%1, %1};" : "=l"(wd[1]) : "f"(w4.y));
            asm("mov.b64 %0, {%1, %1};" : "=l"(wd[2]) : "f"(w4.z));
            asm("mov.b64 %0, {%1, %1};" : "=l"(wd[3]) : "f"(w4.w));
            u64 xp[4];
#pragma unroll
            for (int p = 0; p < 4; p++)
                xp[p] = *reinterpret_cast<const u64*>(&xs[k][rg * 8 + 2 * p]);
#pragma unroll
            for (int p = 0; p < 4; p++)
#pragma unroll
                for (int c = 0; c < 4; c++)
                    asm("fma.rn.f32x2 %0, %1, %2, %0;" : "+l"(acc[p][c]) : "l"(xp[p]), "l"(wd[c]));
        }
    }
#pragma unroll
    for (int p = 0; p < 4; p++) {
        float lo[4], hi[4];
#pragma unroll
        for (int c = 0; c < 4; c++)
            asm("mov.b64 {%0, %1}, %2;" : "=f"(lo[c]), "=f"(hi[c]) : "l"(acc[p][c]));
        int rla = rg * 8 + 2 * p;
        int ga = rows[rla], gb2 = rows[rla + 1];
        float da = d_dinv[ga], db = d_dinv[gb2];
        float4 oa = make_float4(da * lo[0], da * lo[1], da * lo[2], da * lo[3]);
        float4 ob = make_float4(db * hi[0], db * hi[1], db * hi[2], db * hi[3]);
        *reinterpret_cast<float4*>(&d_xw2[(size_t)ga * H2 + cg * 4])  = oa;
        *reinterpret_cast<float4*>(&d_xw2[(size_t)gb2 * H2 + cg * 4]) = ob;
    }
}

// ---------------- layer-2 max aggregation (HOST nodes; no barriers) --------
__global__ void k_agg2(const int* __restrict__ hidx, const float* __restrict__ b2) {
    int hi = blockIdx.x;
    int t = threadIdx.x;       // 64
    int node = __ldg(&hidx[hi]);
    float m = d_xw2[(size_t)node * H2 + t];
    int e0 = d_off[node], e1 = d_off[node + 1];
    int e = e0;
    for (; e + 8 <= e1; e += 8) {
        int s0 = __ldg(&d_csr[e]);
        int s1 = __ldg(&d_csr[e + 1]);
        int s2 = __ldg(&d_csr[e + 2]);
        int s3 = __ldg(&d_csr[e + 3]);
        int s4 = __ldg(&d_csr[e + 4]);
        int s5 = __ldg(&d_csr[e + 5]);
        int s6 = __ldg(&d_csr[e + 6]);
        int s7 = __ldg(&d_csr[e + 7]);
        float v0 = __ldg(&d_xw2[(size_t)s0 * H2 + t]);
        float v1 = __ldg(&d_xw2[(size_t)s1 * H2 + t]);
        float v2 = __ldg(&d_xw2[(size_t)s2 * H2 + t]);
        float v3 = __ldg(&d_xw2[(size_t)s3 * H2 + t]);
        float v4 = __ldg(&d_xw2[(size_t)s4 * H2 + t]);
        float v5 = __ldg(&d_xw2[(size_t)s5 * H2 + t]);
        float v6 = __ldg(&d_xw2[(size_t)s6 * H2 + t]);
        float v7 = __ldg(&d_xw2[(size_t)s7 * H2 + t]);
        float m0 = fmaxf(fmaxf(v0, v1), fmaxf(v2, v3));
        float m1 = fmaxf(fmaxf(v4, v5), fmaxf(v6, v7));
        m = fmaxf(m, fmaxf(m0, m1));
    }
    for (; e < e1; e++)
        m = fmaxf(m, __ldg(&d_xw2[(size_t)__ldg(&d_csr[e]) * H2 + t]));
    d_x2h[(size_t)hi * H2 + t] = fmaxf(d_dinv[node] * m + b2[t], 0.f);
}

// ---------------- fused self attention (r12 proven form) -------------------
template <int F, int H>
__global__ void k_attn(const float* __restrict__ v, const int* __restrict__ hidx,
                       const float* __restrict__ aW, const float* __restrict__ ab,
                       const float* __restrict__ fW, const float* __restrict__ fb,
                       const float* __restrict__ gW, const float* __restrict__ gb) {
    int b = blockIdx.x;
    int t = threadIdx.x;           // 256
    int lane = t & 31, w = t >> 5; // 8 warps

    __shared__ float vsT[F][14];
    __shared__ float ls[NHOST * H];
    __shared__ float fs[NHOST * H];
    __shared__ float mx[NHOST], rinv[NHOST];
    __shared__ float outs[H];
    __shared__ float gs[H1];

    for (int i = t; i < NHOST * F; i += 256) {
        int h = i / F, f = i % F;
        int row = hidx ? hidx[b * NHOST + h] : (b * NHOST + h);
        vsT[f][h] = v[(size_t)row * F + f];
    }
    for (int f = t; f < F; f += 256) vsT[f][13] = 0.f;
    gs[t] = d_g[(size_t)b * H1 + t];
    __syncthreads();

    if (t < H) {
        u64 aLp[7], fVp[7];
#pragma unroll
        for (int p = 0; p < 7; p++) { aLp[p] = 0ull; fVp[p] = 0ull; }
        for (int f = 0; f < F; f += 4) {
            float wa[4], wf[4];
#pragma unroll
            for (int j = 0; j < 4; j++) {
                wa[j] = __ldg(&aW[(f + j) * H + t]);
                wf[j] = __ldg(&fW[(f + j) * H + t]);
            }
#pragma unroll
            for (int j = 0; j < 4; j++) {
                u64 wa2, wf2;
                asm("mov.b64 %0, {%1, %1};" : "=l"(wa2) : "f"(wa[j]));
                asm("mov.b64 %0, {%1, %1};" : "=l"(wf2) : "f"(wf[j]));
#pragma unroll
                for (int p = 0; p < 7; p++) {
                    u64 xv = *reinterpret_cast<const u64*>(&vsT[f + j][2 * p]);
                    asm("fma.rn.f32x2 %0, %1, %2, %0;" : "+l"(aLp[p]) : "l"(xv), "l"(wa2));
                    asm("fma.rn.f32x2 %0, %1, %2, %0;" : "+l"(fVp[p]) : "l"(xv), "l"(wf2));
                }
            }
        }
        float abv = __ldg(&ab[t]), fbv = __ldg(&fb[t]);
#pragma unroll
        for (int p = 0; p < 7; p++) {
            float alo, ahi, flo, fhi;
            asm("mov.b64 {%0, %1}, %2;" : "=f"(alo), "=f"(ahi) : "l"(aLp[p]));
            asm("mov.b64 {%0, %1}, %2;" : "=f"(flo), "=f"(fhi) : "l"(fVp[p]));
            ls[(2 * p) * H + t] = alo + abv;
            fs[(2 * p) * H + t] = flo + fbv;
            if (2 * p + 1 < NHOST) {
                ls[(2 * p + 1) * H + t] = ahi + abv;
                fs[(2 * p + 1) * H + t] = fhi + fbv;
            }
        }
    }
    __syncthreads();

    for (int h = w; h < NHOST; h += 8) {
        float m = -1e30f;
        for (int j = lane; j < H; j += 32) m = fmaxf(m, ls[h * H + j]);
#pragma unroll
        for (int d = 16; d > 0; d >>= 1) m = fmaxf(m, __shfl_xor_sync(0xffffffffu, m, d));
        if (lane == 0) mx[h] = m;
    }
    __syncthreads();
    for (int i = t; i < NHOST * H; i += 256) ls[i] = expf(ls[i] - mx[i / H]);
    __syncthreads();
    for (int h = w; h < NHOST; h += 8) {
        float s = 0.f;
        for (int j = lane; j < H; j += 32) s += ls[h * H + j];
#pragma unroll
        for (int d = 16; d > 0; d >>= 1) s += __shfl_xor_sync(0xffffffffu, s, d);
        if (lane == 0) rinv[h] = 1.0f / s;
    }
    __syncthreads();

    if (t < H) {
        float o = 0.f;
#pragma unroll
        for (int h = 0; h < NHOST; h++)
            o += ls[h * H + t] * rinv[h] * fs[h * H + t];
        outs[t] = o;
    }
    __syncthreads();

    float a0 = __ldg(&gb[t]), a1 = 0.f, a2 = 0.f, a3 = 0.f;
    for (int k = 0; k < H; k += 4) {
        a0 += outs[k]     * __ldg(&gW[(k)     * H1 + t]);
        a1 += outs[k + 1] * __ldg(&gW[(k + 1) * H1 + t]);
        a2 += outs[k + 2] * __ldg(&gW[(k + 2) * H1 + t]);
        a3 += outs[k + 3] * __ldg(&gW[(k + 3) * H1 + t]);
    }
    for (int k = 0; k < H1; k += 4) {
        a0 += gs[k]     * __ldg(&gW[(H + k)     * H1 + t]);
        a1 += gs[k + 1] * __ldg(&gW[(H + k + 1) * H1 + t]);
        a2 += gs[k + 2] * __ldg(&gW[(H + k + 2) * H1 + t]);
        a3 += gs[k + 3] * __ldg(&gW[(H + k + 3) * H1 + t]);
    }
    d_g[(size_t)b * H1 + t] = gs[t] + (a0 + a1) + (a2 + a3);
}

// ---------------- stage-2 attention + head fused ----------------------------
__global__ void k_attn2h(const float* __restrict__ v,
                         const float* __restrict__ aW, const float* __restrict__ ab,
                         const float* __restrict__ fW, const float* __restrict__ fb,
                         const float* __restrict__ gW, const float* __restrict__ gb,
                         const float* __restrict__ o1W, const float* __restrict__ o1b,
                         const float* __restrict__ o2W, const float* __restrict__ o2b,
                         float* __restrict__ out) {
    constexpr int F = H2, H = H2;
    int b = blockIdx.x;
    int t = threadIdx.x;           // 256
    int lane = t & 31, w = t >> 5; // 8 warps

    __shared__ float vsT[F][14];
    __shared__ float ls[NHOST * H];
    __shared__ float fs[NHOST * H];
    __shared__ float mx[NHOST], rinv[NHOST];
    __shared__ float outs[H];
    __shared__ float gs[H1];
    __shared__ float gn[H1];
    __shared__ float rs[64];

    for (int i = t; i < NHOST * F; i += 256) {
        int h = i / F, f = i % F;
        vsT[f][h] = v[(size_t)(b * NHOST + h) * F + f];
    }
    for (int f = t; f < F; f += 256) vsT[f][13] = 0.f;
    gs[t] = d_g[(size_t)b * H1 + t];
    __syncthreads();

    if (t < H) {
        u64 aLp[7], fVp[7];
#pragma unroll
        for (int p = 0; p < 7; p++) { aLp[p] = 0ull; fVp[p] = 0ull; }
        for (int f = 0; f < F; f += 4) {
            float wa[4], wf[4];
#pragma unroll
            for (int j = 0; j < 4; j++) {
                wa[j] = __ldg(&aW[(f + j) * H + t]);
                wf[j] = __ldg(&fW[(f + j) * H + t]);
            }
#pragma unroll
            for (int j = 0; j < 4; j++) {
                u64 wa2, wf2;
                asm("mov.b64 %0, {%1, %1};" : "=l"(wa2) : "f"(wa[j]));
                asm("mov.b64 %0, {%1, %1};" : "=l"(wf2) : "f"(wf[j]));
#pragma unroll
                for (int p = 0; p < 7; p++) {
                    u64 xv = *reinterpret_cast<const u64*>(&vsT[f + j][2 * p]);
                    asm("fma.rn.f32x2 %0, %1, %2, %0;" : "+l"(aLp[p]) : "l"(xv), "l"(wa2));
                    asm("fma.rn.f32x2 %0, %1, %2, %0;" : "+l"(fVp[p]) : "l"(xv), "l"(wf2));
                }
            }
        }
        float abv = __ldg(&ab[t]), fbv = __ldg(&fb[t]);
#pragma unroll
        for (int p = 0; p < 7; p++) {
            float alo, ahi, flo, fhi;
            asm("mov.b64 {%0, %1}, %2;" : "=f"(alo), "=f"(ahi) : "l"(aLp[p]));
            asm("mov.b64 {%0, %1}, %2;" : "=f"(flo), "=f"(fhi) : "l"(fVp[p]));
            ls[(2 * p) * H + t] = alo + abv;
            fs[(2 * p) * H + t] = flo + fbv;
            if (2 * p + 1 < NHOST) {
                ls[(2 * p + 1) * H + t] = ahi + abv;
                fs[(2 * p + 1) * H + t] = fhi + fbv;
            }
        }
    }
    __syncthreads();

    for (int h = w; h < NHOST; h += 8) {
        float m = -1e30f;
        for (int j = lane; j < H; j += 32) m = fmaxf(m, ls[h * H + j]);
#pragma unroll
        for (int d = 16; d > 0; d >>= 1) m = fmaxf(m, __shfl_xor_sync(0xffffffffu, m, d));
        if (lane == 0) mx[h] = m;
    }
    __syncthreads();
    for (int i = t; i < NHOST * H; i += 256) ls[i] = expf(ls[i] - mx[i / H]);
    __syncthreads();
    for (int h = w; h < NHOST; h += 8) {
        float s = 0.f;
        for (int j = lane; j < H; j += 32) s += ls[h * H + j];
#pragma unroll
        for (int d = 16; d > 0; d >>= 1) s += __shfl_xor_sync(0xffffffffu, s, d);
        if (lane == 0) rinv[h] = 1.0f / s;
    }
    __syncthreads();

    if (t < H) {
        float o = 0.f;
#pragma unroll
        for (int h = 0; h < NHOST; h++)
            o += ls[h * H + t] * rinv[h] * fs[h * H + t];
        outs[t] = o;
    }
    __syncthreads();

    float a0 = __ldg(&gb[t]), a1 = 0.f, a2 = 0.f, a3 = 0.f;
    for (int k = 0; k < H; k += 4) {
        a0 += outs[k]     * __ldg(&gW[(k)     * H1 + t]);
        a1 += outs[k + 1] * __ldg(&gW[(k + 1) * H1 + t]);
        a2 += outs[k + 2] * __ldg(&gW[(k + 2) * H1 + t]);
        a3 += outs[k + 3] * __ldg(&gW[(k + 3) * H1 + t]);
    }
    for (int k = 0; k < H1; k += 4) {
        a0 += gs[k]     * __ldg(&gW[(H + k)     * H1 + t]);
        a1 += gs[k + 1] * __ldg(&gW[(H + k + 1) * H1 + t]);
        a2 += gs[k + 2] * __ldg(&gW[(H + k + 2) * H1 + t]);
        a3 += gs[k + 3] * __ldg(&gW[(H + k + 3) * H1 + t]);
    }
    gn[t] = gs[t] + (a0 + a1) + (a2 + a3);
    __syncthreads();

    if (t < 64) {
        float h0 = __ldg(&o1b[t]), h1 = 0.f, h2 = 0.f, h3 = 0.f;
        for (int k = 0; k < H1; k += 4) {
            h0 += gn[k]     * __ldg(&o1W[(k)     * H2 + t]);
            h1 += gn[k + 1] * __ldg(&o1W[(k + 1) * H2 + t]);
            h2 += gn[k + 2] * __ldg(&o1W[(k + 2) * H2 + t]);
            h3 += gn[k + 3] * __ldg(&o1W[(k + 3) * H2 + t]);
        }
        float acc = (h0 + h1) + (h2 + h3);
        rs[t] = fmaxf(acc, 0.f) * __ldg(&o2W[t]);
    }
    __syncthreads();
    if (t < 32) {
        float s = rs[t] + rs[t + 32];
#pragma unroll
        for (int d = 16; d > 0; d >>= 1) s += __shfl_down_sync(0xffffffffu, s, d);
        if (t == 0) out[b] = s + __ldg(&o2b[0]);
    }
}

// ---------------- launch: multi-stream overlapped DAG ----------------------
extern "C" void kernel_launch(void* const* d_in, const int* in_sizes, int n_in,
                              void* d_out, int out_size) {
    const float* x       = (const float*)d_in[0];
    const int*   ei      = (const int*)d_in[1];
    const int*   hostidx = (const int*)d_in[2];
    const float* W1 = (const float*)d_in[3];
    const float* b1 = (const float*)d_in[4];
    const float* W2 = (const float*)d_in[5];
    const float* b2 = (const float*)d_in[6];
    const float* a0W = (const float*)d_in[7];  const float* a0b = (const float*)d_in[8];
    const float* f0W = (const float*)d_in[9];  const float* f0b = (const float*)d_in[10];
    const float* g0W = (const float*)d_in[11]; const float* g0b = (const float*)d_in[12];
    const float* a1W = (const float*)d_in[13]; const float* a1b = (const float*)d_in[14];
    const float* f1W = (const float*)d_in[15]; const float* f1b = (const float*)d_in[16];
    const float* g1W = (const float*)d_in[17]; const float* g1b = (const float*)d_in[18];
    const float* a2W = (const float*)d_in[19]; const float* a2b = (const float*)d_in[20];
    const float* f2W = (const float*)d_in[21]; const float* f2b = (const float*)d_in[22];
    const float* g2W = (const float*)d_in[23]; const float* g2b = (const float*)d_in[24];
    const float* o1W = (const float*)d_in[25]; const float* o1b = (const float*)d_in[26];
    const float* o2W = (const float*)d_in[27]; const float* o2b = (const float*)d_in[28];
    float* out = (float*)d_out;

    const int* src = ei;
    const int* dst = ei + EE;

    float* x1_ptr;  cudaGetSymbolAddress((void**)&x1_ptr,  d_x1);
    float* x2h_ptr; cudaGetSymbolAddress((void**)&x2h_ptr, d_x2h);

    cudaStream_t sB, sC;
    cudaStreamCreateWithFlags(&sB, cudaStreamNonBlocking);
    cudaStreamCreateWithFlags(&sC, cudaStreamNonBlocking);
    cudaEvent_t eZero, eDinv, eG1, eA0, eB2;
    cudaEventCreateWithFlags(&eZero, cudaEventDisableTiming);
    cudaEventCreateWithFlags(&eDinv, cudaEventDisableTiming);
    cudaEventCreateWithFlags(&eG1,   cudaEventDisableTiming);
    cudaEventCreateWithFlags(&eA0,   cudaEventDisableTiming);
    cudaEventCreateWithFlags(&eB2,   cudaEventDisableTiming);

    // main stream (0): graph build chain
    k_zero<<<ZN / 256, 256>>>();
    cudaEventRecord(eZero, 0);

    // stream C: attn0 — only needs d_g=0 and x
    cudaStreamWaitEvent(sC, eZero, 0);
    k_attn<IN_F, H1><<<BB, 256, 0, sC>>>(x, hostidx, a0W, a0b, f0W, f0b, g0W, g0b);
    cudaEventRecord(eA0, sC);

    k_count_mh<<<(EE + 255) / 256, 256>>>(dst, hostidx);
    k_dinv<<<NN / 256, 256>>>();
    cudaEventRecord(eDinv, 0);

    // stream B: gemm1 — needs dinv only; runs under scan/fill/mklist
    cudaStreamWaitEvent(sB, eDinv, 0);
    k_gemm1<<<NN / G1R, 256, 0, sB>>>(x, W1);
    cudaEventRecord(eG1, sB);

    k_scan1<<<NB, 256>>>();
    k_scan2<<<1, 256>>>();
    k_scan3<<<NB, 256>>>();
    k_fill_me<<<(EE + 255) / 256, 256>>>(src, dst);
    k_mklist<<<NN / 256, 256>>>();

    // agg1 needs gemm1 (xw) + graph build
    cudaStreamWaitEvent(0, eG1, 0);
    k_agg1<<<NN, 256>>>(b1);
    cudaEventRecord(eDinv, 0);   // reuse event: "after agg1"

    // stream B: gemm2 + agg2 — parallel with attn1 (independent of g)
    cudaStreamWaitEvent(sB, eDinv, 0);
    k_gemm2<<<(NN + G2R - 1) / G2R, 256, 0, sB>>>(W2);
    k_agg2<<<BB * NHOST, 64, 0, sB>>>(hostidx, b2);
    cudaEventRecord(eB2, sB);

    // main: attn1 — needs x1 (agg1, main order) + g (attn0 via eA0)
    cudaStreamWaitEvent(0, eA0, 0);
    k_attn<H1, H1><<<BB, 256>>>(x1_ptr, hostidx, a1W, a1b, f1W, f1b, g1W, g1b);

    // attn2+head — needs g (main order) + x2h (eB2)
    cudaStreamWaitEvent(0, eB2, 0);
    k_attn2h<<<BB, 256>>>(x2h_ptr, a2W, a2b, f2W, f2b, g2W, g2b,
                          o1W, o1b, o2W, o2b, out);

    cudaEventDestroy(eZero);
    cudaEventDestroy(eDinv);
    cudaEventDestroy(eG1);
    cudaEventDestroy(eA0);
    cudaEventDestroy(eB2);
    cudaStreamDestroy(sB);
    cudaStreamDestroy(sC);
}

// round 17
// speedup vs baseline: 1.4079x; 1.1671x over previous
#include <cuda_runtime.h>
#include <math.h>

#define NN 51200      // nodes
#define EE 409600     // edges (without self loops)
#define BB 256        // batch
#define NHOST 13
#define IN_F 64
#define H1 256
#define H2 64
#define ZN 65536      // max(NN, BB*H1) — elements to zero
#define NB 200        // NN / 256 scan blocks

typedef unsigned long long u64;

// ---------------- scratch (static device globals; no runtime alloc) -------
__device__ int   d_cnt[NN];
__device__ int   d_off[NN + 1];
__device__ int   d_cur[NN];
__device__ int   d_csr[EE];
__device__ int   d_flag[NN];
__device__ int   d_ishost[NN];
__device__ int   d_list[NN];
__device__ int   d_nf;
__device__ int   d_bsum[NB];
__device__ int   d_bbase[NB];
__device__ float d_dinv[NN];
__device__ float d_xw[(size_t)NN * H1];    // dinv * (x @ W1)
__device__ float d_x1[(size_t)NN * H1];    // relu(agg1 + b1) on frontier rows
__device__ float d_xw2[(size_t)NN * H2];   // dinv * (x1 @ W2), frontier rows only
__device__ float d_x2h[(size_t)BB * NHOST * H2];
__device__ float d_g[(size_t)BB * H1];     // global state

// ---------------- zero ------------------------------------------------------
__global__ void k_zero() {
    int i = blockIdx.x * blockDim.x + threadIdx.x;
    if (i < NN) { d_cnt[i] = 0; d_flag[i] = 0; d_ishost[i] = 0; }
    if (i < BB * H1) d_g[i] = 0.f;
    if (i == 0) d_nf = 0;
}

__global__ void k_count_mh(const int* __restrict__ dst, const int* __restrict__ hidx) {
    int e = blockIdx.x * blockDim.x + threadIdx.x;
    if (e < EE) atomicAdd(&d_cnt[dst[e]], 1);
    if (e < BB * NHOST) {
        int n = hidx[e];
        d_ishost[n] = 1;
        d_flag[n] = 1;
    }
}

__global__ void k_dinv() {
    int i = blockIdx.x * blockDim.x + threadIdx.x;
    if (i < NN) d_dinv[i] = rsqrtf((float)(d_cnt[i] + 1));  // +1 self loop
}

// ---------------- parallel 3-phase scan -------------------------------------
__global__ void k_scan1() {
    __shared__ int sh[256];
    int t = threadIdx.x;
    sh[t] = d_cnt[blockIdx.x * 256 + t];
    __syncthreads();
#pragma unroll
    for (int d = 128; d > 0; d >>= 1) {
        if (t < d) sh[t] += sh[t + d];
        __syncthreads();
    }
    if (t == 0) d_bsum[blockIdx.x] = sh[0];
}

__global__ void k_scan2() {
    __shared__ int sh[256];
    int t = threadIdx.x;
    int v = (t < NB) ? d_bsum[t] : 0;
    sh[t] = v;
    __syncthreads();
#pragma unroll
    for (int d = 1; d < 256; d <<= 1) {
        int x = sh[t];
        int add = (t >= d) ? sh[t - d] : 0;
        __syncthreads();
        sh[t] = x + add;
        __syncthreads();
    }
    if (t < NB) d_bbase[t] = sh[t] - v;  // exclusive
}

__global__ void k_scan3() {
    __shared__ int sh[256];
    int t = threadIdx.x;
    int i = blockIdx.x * 256 + t;
    int c = d_cnt[i];
    sh[t] = c;
    __syncthreads();
#pragma unroll
    for (int d = 1; d < 256; d <<= 1) {
        int x = sh[t];
        int add = (t >= d) ? sh[t - d] : 0;
        __syncthreads();
        sh[t] = x + add;
        __syncthreads();
    }
    int off = d_bbase[blockIdx.x] + sh[t] - c;
    d_off[i] = off;
    d_cur[i] = off;
    if (i == 0) d_off[NN] = EE;
}

__global__ void k_fill_me(const int* __restrict__ src, const int* __restrict__ dst) {
    int e = blockIdx.x * blockDim.x + threadIdx.x;
    if (e < EE) {
        int d = dst[e];
        int s = src[e];
        int p = atomicAdd(&d_cur[d], 1);
        d_csr[p] = s;
        if (d_ishost[d]) d_flag[s] = 1;
    }
}

__global__ void k_mklist() {
    int i = blockIdx.x * blockDim.x + threadIdx.x;
    if (i < NN && d_flag[i]) {
        int p = atomicAdd(&d_nf, 1);
        d_list[p] = i;
    }
}

// ---------------- GEMM1: xw = dinv * (x @ W1)  [51200,64]x[64,256] ---------
#define G1R 32
__global__ void __launch_bounds__(256, 4) k_gemm1(
        const float* __restrict__ x, const float* __restrict__ W1) {
    __shared__ float xs[IN_F][G1R + 2];
    int r0 = blockIdx.x * G1R;
    int t = threadIdx.x; // 256
    int rg = t >> 6;
    int cg = t & 63;
    for (int i = t; i < G1R * IN_F; i += 256) {
        int r = i >> 6, k = i & 63;
        xs[k][r] = x[(size_t)(r0 + r) * IN_F + k];
    }
    __syncthreads();
    u64 acc[4][4];
#pragma unroll
    for (int p = 0; p < 4; p++)
#pragma unroll
        for (int c = 0; c < 4; c++) acc[p][c] = 0ull;
    for (int k = 0; k < IN_F; k++) {
        float4 w4 = *reinterpret_cast<const float4*>(&W1[k * H1 + cg * 4]);
        u64 wd[4];
        asm("mov.b64 %0, {%1, %1};" : "=l"(wd[0]) : "f"(w4.x));
        asm("mov.b64 %0, {%1, %1};" : "=l"(wd[1]) : "f"(w4.y));
        asm("mov.b64 %0, {%1, %1};" : "=l"(wd[2]) : "f"(w4.z));
        asm("mov.b64 %0, {%1, %1};" : "=l"(wd[3]) : "f"(w4.w));
        u64 xp[4];
#pragma unroll
        for (int p = 0; p < 4; p++)
            xp[p] = *reinterpret_cast<const u64*>(&xs[k][rg * 8 + 2 * p]);
#pragma unroll
        for (int p = 0; p < 4; p++)
#pragma unroll
            for (int c = 0; c < 4; c++)
                asm("fma.rn.f32x2 %0, %1, %2, %0;" : "+l"(acc[p][c]) : "l"(xp[p]), "l"(wd[c]));
    }
#pragma unroll
    for (int p = 0; p < 4; p++) {
        float lo[4], hi[4];
#pragma unroll
        for (int c = 0; c < 4; c++)
            asm("mov.b64 {%0, %1}, %2;" : "=f"(lo[c]), "=f"(hi[c]) : "l"(acc[p][c]));
        int ra = r0 + rg * 8 + 2 * p;
        float da = d_dinv[ra], db = d_dinv[ra + 1];
        float4 oa = make_float4(da * lo[0], da * lo[1], da * lo[2], da * lo[3]);
        float4 ob = make_float4(db * hi[0], db * hi[1], db * hi[2], db * hi[3]);
        *reinterpret_cast<float4*>(&d_xw[(size_t)ra * H1 + cg * 4])       = oa;
        *reinterpret_cast<float4*>(&d_xw[(size_t)(ra + 1) * H1 + cg * 4]) = ob;
    }
}

// ---------------- layer-1 max aggregation (r12 proven form) ----------------
__global__ void k_agg1(const float* __restrict__ b1) {
    int bi = blockIdx.x;
    if (bi >= d_nf) return;
    int i = d_list[bi];
    int t = threadIdx.x; // 256
    float m = d_xw[(size_t)i * H1 + t];
    int e0 = d_off[i], e1 = d_off[i + 1];
    int e = e0;
    for (; e + 8 <= e1; e += 8) {
        int s0 = __ldg(&d_csr[e]);
        int s1 = __ldg(&d_csr[e + 1]);
        int s2 = __ldg(&d_csr[e + 2]);
        int s3 = __ldg(&d_csr[e + 3]);
        int s4 = __ldg(&d_csr[e + 4]);
        int s5 = __ldg(&d_csr[e + 5]);
        int s6 = __ldg(&d_csr[e + 6]);
        int s7 = __ldg(&d_csr[e + 7]);
        float v0 = __ldg(&d_xw[(size_t)s0 * H1 + t]);
        float v1 = __ldg(&d_xw[(size_t)s1 * H1 + t]);
        float v2 = __ldg(&d_xw[(size_t)s2 * H1 + t]);
        float v3 = __ldg(&d_xw[(size_t)s3 * H1 + t]);
        float v4 = __ldg(&d_xw[(size_t)s4 * H1 + t]);
        float v5 = __ldg(&d_xw[(size_t)s5 * H1 + t]);
        float v6 = __ldg(&d_xw[(size_t)s6 * H1 + t]);
        float v7 = __ldg(&d_xw[(size_t)s7 * H1 + t]);
        float m0 = fmaxf(fmaxf(v0, v1), fmaxf(v2, v3));
        float m1 = fmaxf(fmaxf(v4, v5), fmaxf(v6, v7));
        m = fmaxf(m, fmaxf(m0, m1));
    }
    for (; e < e1; e++)
        m = fmaxf(m, __ldg(&d_xw[(size_t)__ldg(&d_csr[e]) * H1 + t]));
    d_x1[(size_t)i * H1 + t] = fmaxf(d_dinv[i] * m + b1[t], 0.f);
}

// ---------------- GEMM2 on frontier rows: xw2 = dinv * (x1 @ W2) -----------
#define G2R 128
__global__ void __launch_bounds__(256, 4) k_gemm2(const float* __restrict__ W2) {
    int r0 = blockIdx.x * G2R;
    int nf = d_nf;
    if (r0 >= nf) return;
    __shared__ float xs[64][G2R + 2];
    __shared__ int rows[G2R];
    int t = threadIdx.x;      // 256
    int rg = t >> 4;
    int cg = t & 15;
    if (t < G2R) rows[t] = d_list[min(r0 + t, nf - 1)];
    __syncthreads();
    u64 acc[4][4];
#pragma unroll
    for (int p = 0; p < 4; p++)
#pragma unroll
        for (int c = 0; c < 4; c++) acc[p][c] = 0ull;
    for (int kc = 0; kc < H1; kc += 64) {
        __syncthreads();
        for (int i = t; i < G2R * 64; i += 256) {
            int r = i >> 6, k = i & 63;
            xs[k][r] = d_x1[(size_t)rows[r] * H1 + kc + k];
        }
        __syncthreads();
        for (int k = 0; k < 64; k++) {
            float4 w4 = *reinterpret_cast<const float4*>(&W2[(kc + k) * H2 + cg * 4]);
            u64 wd[4];
            asm("mov.b64 %0, {%1, %1};" : "=l"(wd[0]) : "f"(w4.x));
            asm("mov.b64 %0, {%1, %1};" : "=l"(wd[1]) : "f"(w4.y));
            asm("mov.b64 %0, {%1, %1};" : "=l"(wd[2]) : "f"(w4.z));
            asm("mov.b64 %0, {%1, %1};" : "=l"(wd[3]) : "f"(w4.w));
            u64 xp[4];
#pragma unroll
            for (int p = 0; p < 4; p++)
                xp[p] = *reinterpret_cast<const u64*>(&xs[k][rg * 8 + 2 * p]);
#pragma unroll
            for (int p = 0; p < 4; p++)
#pragma unroll
                for (int c = 0; c < 4; c++)
                    asm("fma.rn.f32x2 %0, %1, %2, %0;" : "+l"(acc[p][c]) : "l"(xp[p]), "l"(wd[c]));
        }
    }
#pragma unroll
    for (int p = 0; p < 4; p++) {
        float lo[4], hi[4];
#pragma unroll
        for (int c = 0; c < 4; c++)
            asm("mov.b64 {%0, %1}, %2;" : "=f"(lo[c]), "=f"(hi[c]) : "l"(acc[p][c]));
        int rla = rg * 8 + 2 * p;
        int ga = rows[rla], gb2 = rows[rla + 1];
        float da = d_dinv[ga], db = d_dinv[gb2];
        float4 oa = make_float4(da * lo[0], da * lo[1], da * lo[2], da * lo[3]);
        float4 ob = make_float4(db * hi[0], db * hi[1], db * hi[2], db * hi[3]);
        *reinterpret_cast<float4*>(&d_xw2[(size_t)ga * H2 + cg * 4])  = oa;
        *reinterpret_cast<float4*>(&d_xw2[(size_t)gb2 * H2 + cg * 4]) = ob;
    }
}

// ---------------- layer-2 max aggregation (HOST nodes; no barriers) --------
__global__ void k_agg2(const int* __restrict__ hidx, const float* __restrict__ b2) {
    int hi = blockIdx.x;
    int t = threadIdx.x;       // 64
    int node = __ldg(&hidx[hi]);
    float m = d_xw2[(size_t)node * H2 + t];
    int e0 = d_off[node], e1 = d_off[node + 1];
    int e = e0;
    for (; e + 8 <= e1; e += 8) {
        int s0 = __ldg(&d_csr[e]);
        int s1 = __ldg(&d_csr[e + 1]);
        int s2 = __ldg(&d_csr[e + 2]);
        int s3 = __ldg(&d_csr[e + 3]);
        int s4 = __ldg(&d_csr[e + 4]);
        int s5 = __ldg(&d_csr[e + 5]);
        int s6 = __ldg(&d_csr[e + 6]);
        int s7 = __ldg(&d_csr[e + 7]);
        float v0 = __ldg(&d_xw2[(size_t)s0 * H2 + t]);
        float v1 = __ldg(&d_xw2[(size_t)s1 * H2 + t]);
        float v2 = __ldg(&d_xw2[(size_t)s2 * H2 + t]);
        float v3 = __ldg(&d_xw2[(size_t)s3 * H2 + t]);
        float v4 = __ldg(&d_xw2[(size_t)s4 * H2 + t]);
        float v5 = __ldg(&d_xw2[(size_t)s5 * H2 + t]);
        float v6 = __ldg(&d_xw2[(size_t)s6 * H2 + t]);
        float v7 = __ldg(&d_xw2[(size_t)s7 * H2 + t]);
        float m0 = fmaxf(fmaxf(v0, v1), fmaxf(v2, v3));
        float m1 = fmaxf(fmaxf(v4, v5), fmaxf(v6, v7));
        m = fmaxf(m, fmaxf(m0, m1));
    }
    for (; e < e1; e++)
        m = fmaxf(m, __ldg(&d_xw2[(size_t)__ldg(&d_csr[e]) * H2 + t]));
    d_x2h[(size_t)hi * H2 + t] = fmaxf(d_dinv[node] * m + b2[t], 0.f);
}

// ---------------- fused self attention (r12 form; used for stage 0) --------
template <int F, int H>
__global__ void k_attn(const float* __restrict__ v, const int* __restrict__ hidx,
                       const float* __restrict__ aW, const float* __restrict__ ab,
                       const float* __restrict__ fW, const float* __restrict__ fb,
                       const float* __restrict__ gW, const float* __restrict__ gb) {
    int b = blockIdx.x;
    int t = threadIdx.x;           // 256
    int lane = t & 31, w = t >> 5; // 8 warps

    __shared__ float vsT[F][14];
    __shared__ float ls[NHOST * H];
    __shared__ float fs[NHOST * H];
    __shared__ float mx[NHOST], rinv[NHOST];
    __shared__ float outs[H];
    __shared__ float gs[H1];

    for (int i = t; i < NHOST * F; i += 256) {
        int h = i / F, f = i % F;
        int row = hidx ? hidx[b * NHOST + h] : (b * NHOST + h);
        vsT[f][h] = v[(size_t)row * F + f];
    }
    for (int f = t; f < F; f += 256) vsT[f][13] = 0.f;
    gs[t] = d_g[(size_t)b * H1 + t];
    __syncthreads();

    if (t < H) {
        u64 aLp[7], fVp[7];
#pragma unroll
        for (int p = 0; p < 7; p++) { aLp[p] = 0ull; fVp[p] = 0ull; }
        for (int f = 0; f < F; f += 4) {
            float wa[4], wf[4];
#pragma unroll
            for (int j = 0; j < 4; j++) {
                wa[j] = __ldg(&aW[(f + j) * H + t]);
                wf[j] = __ldg(&fW[(f + j) * H + t]);
            }
#pragma unroll
            for (int j = 0; j < 4; j++) {
                u64 wa2, wf2;
                asm("mov.b64 %0, {%1, %1};" : "=l"(wa2) : "f"(wa[j]));
                asm("mov.b64 %0, {%1, %1};" : "=l"(wf2) : "f"(wf[j]));
#pragma unroll
                for (int p = 0; p < 7; p++) {
                    u64 xv = *reinterpret_cast<const u64*>(&vsT[f + j][2 * p]);
                    asm("fma.rn.f32x2 %0, %1, %2, %0;" : "+l"(aLp[p]) : "l"(xv), "l"(wa2));
                    asm("fma.rn.f32x2 %0, %1, %2, %0;" : "+l"(fVp[p]) : "l"(xv), "l"(wf2));
                }
            }
        }
        float abv = __ldg(&ab[t]), fbv = __ldg(&fb[t]);
#pragma unroll
        for (int p = 0; p < 7; p++) {
            float alo, ahi, flo, fhi;
            asm("mov.b64 {%0, %1}, %2;" : "=f"(alo), "=f"(ahi) : "l"(aLp[p]));
            asm("mov.b64 {%0, %1}, %2;" : "=f"(flo), "=f"(fhi) : "l"(fVp[p]));
            ls[(2 * p) * H + t] = alo + abv;
            fs[(2 * p) * H + t] = flo + fbv;
            if (2 * p + 1 < NHOST) {
                ls[(2 * p + 1) * H + t] = ahi + abv;
                fs[(2 * p + 1) * H + t] = fhi + fbv;
            }
        }
    }
    __syncthreads();

    for (int h = w; h < NHOST; h += 8) {
        float m = -1e30f;
        for (int j = lane; j < H; j += 32) m = fmaxf(m, ls[h * H + j]);
#pragma unroll
        for (int d = 16; d > 0; d >>= 1) m = fmaxf(m, __shfl_xor_sync(0xffffffffu, m, d));
        if (lane == 0) mx[h] = m;
    }
    __syncthreads();
    for (int i = t; i < NHOST * H; i += 256) ls[i] = expf(ls[i] - mx[i / H]);
    __syncthreads();
    for (int h = w; h < NHOST; h += 8) {
        float s = 0.f;
        for (int j = lane; j < H; j += 32) s += ls[h * H + j];
#pragma unroll
        for (int d = 16; d > 0; d >>= 1) s += __shfl_xor_sync(0xffffffffu, s, d);
        if (lane == 0) rinv[h] = 1.0f / s;
    }
    __syncthreads();

    if (t < H) {
        float o = 0.f;
#pragma unroll
        for (int h = 0; h < NHOST; h++)
            o += ls[h * H + t] * rinv[h] * fs[h * H + t];
        outs[t] = o;
    }
    __syncthreads();

    float a0 = __ldg(&gb[t]), a1 = 0.f, a2 = 0.f, a3 = 0.f;
    for (int k = 0; k < H; k += 4) {
        a0 += outs[k]     * __ldg(&gW[(k)     * H1 + t]);
        a1 += outs[k + 1] * __ldg(&gW[(k + 1) * H1 + t]);
        a2 += outs[k + 2] * __ldg(&gW[(k + 2) * H1 + t]);
        a3 += outs[k + 3] * __ldg(&gW[(k + 3) * H1 + t]);
    }
    for (int k = 0; k < H1; k += 4) {
        a0 += gs[k]     * __ldg(&gW[(H + k)     * H1 + t]);
        a1 += gs[k + 1] * __ldg(&gW[(H + k + 1) * H1 + t]);
        a2 += gs[k + 2] * __ldg(&gW[(H + k + 2) * H1 + t]);
        a3 += gs[k + 3] * __ldg(&gW[(H + k + 3) * H1 + t]);
    }
    d_g[(size_t)b * H1 + t] = gs[t] + (a0 + a1) + (a2 + a3);
}

// ---------------- stage-1 attention: 512 threads, in-block k-split ---------
// half 0: f ∈ [0,128) partials; half 1: f ∈ [128,256); combined in smem.
__global__ void __launch_bounds__(512) k_attn1(
        const float* __restrict__ v, const int* __restrict__ hidx,
        const float* __restrict__ aW, const float* __restrict__ ab,
        const float* __restrict__ fW, const float* __restrict__ fb,
        const float* __restrict__ gW, const float* __restrict__ gb) {
    constexpr int F = H1, H = H1;
    int b = blockIdx.x;
    int tid = threadIdx.x;           // 512
    int half = tid >> 8;
    int t = tid & 255;
    int lane = tid & 31, w = tid >> 5;  // 16 warps

    __shared__ float vsT[F][14];     // 14.3KB
    __shared__ float ls[NHOST * H];  // 13.3KB
    __shared__ float fs[NHOST * H];  // 13.3KB
    __shared__ float mx[NHOST], rinv[NHOST];
    __shared__ float outs[H];
    __shared__ float gs[H1];
    __shared__ float pd[2][H1];      // 2KB

    for (int i = tid; i < NHOST * F; i += 512) {
        int h = i / F, f = i % F;
        vsT[f][h] = v[(size_t)hidx[b * NHOST + h] * F + f];
    }
    for (int f = tid; f < F; f += 512) vsT[f][13] = 0.f;
    if (tid < H1) gs[tid] = d_g[(size_t)b * H1 + tid];
    __syncthreads();

    // Phase A: per-half partial accumulation over half the f range
    float alo[7], ahi[7], flo[7], fhi[7];
    {
        u64 aLp[7], fVp[7];
#pragma unroll
        for (int p = 0; p < 7; p++) { aLp[p] = 0ull; fVp[p] = 0ull; }
        int f0 = half * (F / 2);
        for (int f = f0; f < f0 + F / 2; f += 4) {
            float wa[4], wf[4];
#pragma unroll
            for (int j = 0; j < 4; j++) {
                wa[j] = __ldg(&aW[(f + j) * H + t]);
                wf[j] = __ldg(&fW[(f + j) * H + t]);
            }
#pragma unroll
            for (int j = 0; j < 4; j++) {
                u64 wa2, wf2;
                asm("mov.b64 %0, {%1, %1};" : "=l"(wa2) : "f"(wa[j]));
                asm("mov.b64 %0, {%1, %1};" : "=l"(wf2) : "f"(wf[j]));
#pragma unroll
                for (int p = 0; p < 7; p++) {
                    u64 xv = *reinterpret_cast<const u64*>(&vsT[f + j][2 * p]);
                    asm("fma.rn.f32x2 %0, %1, %2, %0;" : "+l"(aLp[p]) : "l"(xv), "l"(wa2));
                    asm("fma.rn.f32x2 %0, %1, %2, %0;" : "+l"(fVp[p]) : "l"(xv), "l"(wf2));
                }
            }
        }
#pragma unroll
        for (int p = 0; p < 7; p++) {
            asm("mov.b64 {%0, %1}, %2;" : "=f"(alo[p]), "=f"(ahi[p]) : "l"(aLp[p]));
            asm("mov.b64 {%0, %1}, %2;" : "=f"(flo[p]), "=f"(fhi[p]) : "l"(fVp[p]));
        }
    }
    // half 0 writes partials
    if (half == 0) {
#pragma unroll
        for (int p = 0; p < 7; p++) {
            ls[(2 * p) * H + t] = alo[p];
            fs[(2 * p) * H + t] = flo[p];
            if (2 * p + 1 < NHOST) {
                ls[(2 * p + 1) * H + t] = ahi[p];
                fs[(2 * p + 1) * H + t] = fhi[p];
            }
        }
    }
    __syncthreads();
    // half 1 adds partials + bias
    if (half == 1) {
        float abv = __ldg(&ab[t]), fbv = __ldg(&fb[t]);
#pragma unroll
        for (int p = 0; p < 7; p++) {
            ls[(2 * p) * H + t] += alo[p] + abv;
            fs[(2 * p) * H + t] += flo[p] + fbv;
            if (2 * p + 1 < NHOST) {
                ls[(2 * p + 1) * H + t] += ahi[p] + abv;
                fs[(2 * p + 1) * H + t] += fhi[p] + fbv;
            }
        }
    }
    __syncthreads();

    // Phase B: softmax stats (16 warps → one pass over 13 hosts)
    if (w < NHOST) {
        float m = -1e30f;
        for (int j = lane; j < H; j += 32) m = fmaxf(m, ls[w * H + j]);
#pragma unroll
        for (int d = 16; d > 0; d >>= 1) m = fmaxf(m, __shfl_xor_sync(0xffffffffu, m, d));
        if (lane == 0) mx[w] = m;
    }
    __syncthreads();
    for (int i = tid; i < NHOST * H; i += 512) ls[i] = expf(ls[i] - mx[i / H]);
    __syncthreads();
    if (w < NHOST) {
        float s = 0.f;
        for (int j = lane; j < H; j += 32) s += ls[w * H + j];
#pragma unroll
        for (int d = 16; d > 0; d >>= 1) s += __shfl_xor_sync(0xffffffffu, s, d);
        if (lane == 0) rinv[w] = 1.0f / s;
    }
    __syncthreads();

    // Phase C: weighted sum
    if (tid < H) {
        float o = 0.f;
#pragma unroll
        for (int h = 0; h < NHOST; h++)
            o += ls[h * H + tid] * rinv[h] * fs[h * H + tid];
        outs[tid] = o;
    }
    __syncthreads();

    // Phase D: k-split matvec. half0 → outs-range, half1 → gs-range.
    {
        const float* cat = half ? gs : outs;
        int koff = half * H;   // gW row offset
        float a0 = 0.f, a1 = 0.f, a2 = 0.f, a3 = 0.f;
        for (int k = 0; k < H; k += 4) {
            a0 += cat[k]     * __ldg(&gW[(size_t)(koff + k)     * H1 + t]);
            a1 += cat[k + 1] * __ldg(&gW[(size_t)(koff + k + 1) * H1 + t]);
            a2 += cat[k + 2] * __ldg(&gW[(size_t)(koff + k + 2) * H1 + t]);
            a3 += cat[k + 3] * __ldg(&gW[(size_t)(koff + k + 3) * H1 + t]);
        }
        pd[half][t] = (a0 + a1) + (a2 + a3);
    }
    __syncthreads();
    if (tid < H1)
        d_g[(size_t)b * H1 + tid] = gs[tid] + __ldg(&gb[tid]) + pd[0][tid] + pd[1][tid];
}

// ---------------- stage-2 attention + head fused ----------------------------
__global__ void k_attn2h(const float* __restrict__ v,
                         const float* __restrict__ aW, const float* __restrict__ ab,
                         const float* __restrict__ fW, const float* __restrict__ fb,
                         const float* __restrict__ gW, const float* __restrict__ gb,
                         const float* __restrict__ o1W, const float* __restrict__ o1b,
                         const float* __restrict__ o2W, const float* __restrict__ o2b,
                         float* __restrict__ out) {
    constexpr int F = H2, H = H2;
    int b = blockIdx.x;
    int t = threadIdx.x;           // 256
    int lane = t & 31, w = t >> 5; // 8 warps

    __shared__ float vsT[F][14];
    __shared__ float ls[NHOST * H];
    __shared__ float fs[NHOST * H];
    __shared__ float mx[NHOST], rinv[NHOST];
    __shared__ float outs[H];
    __shared__ float gs[H1];
    __shared__ float gn[H1];
    __shared__ float rs[64];

    for (int i = t; i < NHOST * F; i += 256) {
        int h = i / F, f = i % F;
        vsT[f][h] = v[(size_t)(b * NHOST + h) * F + f];
    }
    for (int f = t; f < F; f += 256) vsT[f][13] = 0.f;
    gs[t] = d_g[(size_t)b * H1 + t];
    __syncthreads();

    if (t < H) {
        u64 aLp[7], fVp[7];
#pragma unroll
        for (int p = 0; p < 7; p++) { aLp[p] = 0ull; fVp[p] = 0ull; }
        for (int f = 0; f < F; f += 4) {
            float wa[4], wf[4];
#pragma unroll
            for (int j = 0; j < 4; j++) {
                wa[j] = __ldg(&aW[(f + j) * H + t]);
                wf[j] = __ldg(&fW[(f + j) * H + t]);
            }
#pragma unroll
            for (int j = 0; j < 4; j++) {
                u64 wa2, wf2;
                asm("mov.b64 %0, {%1, %1};" : "=l"(wa2) : "f"(wa[j]));
                asm("mov.b64 %0, {%1, %1};" : "=l"(wf2) : "f"(wf[j]));
#pragma unroll
                for (int p = 0; p < 7; p++) {
                    u64 xv = *reinterpret_cast<const u64*>(&vsT[f + j][2 * p]);
                    asm("fma.rn.f32x2 %0, %1, %2, %0;" : "+l"(aLp[p]) : "l"(xv), "l"(wa2));
                    asm("fma.rn.f32x2 %0, %1, %2, %0;" : "+l"(fVp[p]) : "l"(xv), "l"(wf2));
                }
            }
        }
        float abv = __ldg(&ab[t]), fbv = __ldg(&fb[t]);
#pragma unroll
        for (int p = 0; p < 7; p++) {
            float alo, ahi, flo, fhi;
            asm("mov.b64 {%0, %1}, %2;" : "=f"(alo), "=f"(ahi) : "l"(aLp[p]));
            asm("mov.b64 {%0, %1}, %2;" : "=f"(flo), "=f"(fhi) : "l"(fVp[p]));
            ls[(2 * p) * H + t] = alo + abv;
            fs[(2 * p) * H + t] = flo + fbv;
            if (2 * p + 1 < NHOST) {
                ls[(2 * p + 1) * H + t] = ahi + abv;
                fs[(2 * p + 1) * H + t] = fhi + fbv;
            }
        }
    }
    __syncthreads();

    for (int h = w; h < NHOST; h += 8) {
        float m = -1e30f;
        for (int j = lane; j < H; j += 32) m = fmaxf(m, ls[h * H + j]);
#pragma unroll
        for (int d = 16; d > 0; d >>= 1) m = fmaxf(m, __shfl_xor_sync(0xffffffffu, m, d));
        if (lane == 0) mx[h] = m;
    }
    __syncthreads();
    for (int i = t; i < NHOST * H; i += 256) ls[i] = expf(ls[i] - mx[i / H]);
    __syncthreads();
    for (int h = w; h < NHOST; h += 8) {
        float s = 0.f;
        for (int j = lane; j < H; j += 32) s += ls[h * H + j];
#pragma unroll
        for (int d = 16; d > 0; d >>= 1) s += __shfl_xor_sync(0xffffffffu, s, d);
        if (lane == 0) rinv[h] = 1.0f / s;
    }
    __syncthreads();

    if (t < H) {
        float o = 0.f;
#pragma unroll
        for (int h = 0; h < NHOST; h++)
            o += ls[h * H + t] * rinv[h] * fs[h * H + t];
        outs[t] = o;
    }
    __syncthreads();

    float a0 = __ldg(&gb[t]), a1 = 0.f, a2 = 0.f, a3 = 0.f;
    for (int k = 0; k < H; k += 4) {
        a0 += outs[k]     * __ldg(&gW[(k)     * H1 + t]);
        a1 += outs[k + 1] * __ldg(&gW[(k + 1) * H1 + t]);
        a2 += outs[k + 2] * __ldg(&gW[(k + 2) * H1 + t]);
        a3 += outs[k + 3] * __ldg(&gW[(k + 3) * H1 + t]);
    }
    for (int k = 0; k < H1; k += 4) {
        a0 += gs[k]     * __ldg(&gW[(H + k)     * H1 + t]);
        a1 += gs[k + 1] * __ldg(&gW[(H + k + 1) * H1 + t]);
        a2 += gs[k + 2] * __ldg(&gW[(H + k + 2) * H1 + t]);
        a3 += gs[k + 3] * __ldg(&gW[(H + k + 3) * H1 + t]);
    }
    gn[t] = gs[t] + (a0 + a1) + (a2 + a3);
    __syncthreads();

    if (t < 64) {
        float h0 = __ldg(&o1b[t]), h1 = 0.f, h2 = 0.f, h3 = 0.f;
        for (int k = 0; k < H1; k += 4) {
            h0 += gn[k]     * __ldg(&o1W[(k)     * H2 + t]);
            h1 += gn[k + 1] * __ldg(&o1W[(k + 1) * H2 + t]);
            h2 += gn[k + 2] * __ldg(&o1W[(k + 2) * H2 + t]);
            h3 += gn[k + 3] * __ldg(&o1W[(k + 3) * H2 + t]);
        }
        float acc = (h0 + h1) + (h2 + h3);
        rs[t] = fmaxf(acc, 0.f) * __ldg(&o2W[t]);
    }
    __syncthreads();
    if (t < 32) {
        float s = rs[t] + rs[t + 32];
#pragma unroll
        for (int d = 16; d > 0; d >>= 1) s += __shfl_down_sync(0xffffffffu, s, d);
        if (t == 0) out[b] = s + __ldg(&o2b[0]);
    }
}

// ---------------- launch: multi-stream overlapped DAG ----------------------
extern "C" void kernel_launch(void* const* d_in, const int* in_sizes, int n_in,
                              void* d_out, int out_size) {
    const float* x       = (const float*)d_in[0];
    const int*   ei      = (const int*)d_in[1];
    const int*   hostidx = (const int*)d_in[2];
    const float* W1 = (const float*)d_in[3];
    const float* b1 = (const float*)d_in[4];
    const float* W2 = (const float*)d_in[5];
    const float* b2 = (const float*)d_in[6];
    const float* a0W = (const float*)d_in[7];  const float* a0b = (const float*)d_in[8];
    const float* f0W = (const float*)d_in[9];  const float* f0b = (const float*)d_in[10];
    const float* g0W = (const float*)d_in[11]; const float* g0b = (const float*)d_in[12];
    const float* a1W = (const float*)d_in[13]; const float* a1b = (const float*)d_in[14];
    const float* f1W = (const float*)d_in[15]; const float* f1b = (const float*)d_in[16];
    const float* g1W = (const float*)d_in[17]; const float* g1b = (const float*)d_in[18];
    const float* a2W = (const float*)d_in[19]; const float* a2b = (const float*)d_in[20];
    const float* f2W = (const float*)d_in[21]; const float* f2b = (const float*)d_in[22];
    const float* g2W = (const float*)d_in[23]; const float* g2b = (const float*)d_in[24];
    const float* o1W = (const float*)d_in[25]; const float* o1b = (const float*)d_in[26];
    const float* o2W = (const float*)d_in[27]; const float* o2b = (const float*)d_in[28];
    float* out = (float*)d_out;

    const int* src = ei;
    const int* dst = ei + EE;

    float* x1_ptr;  cudaGetSymbolAddress((void**)&x1_ptr,  d_x1);
    float* x2h_ptr; cudaGetSymbolAddress((void**)&x2h_ptr, d_x2h);

    cudaStream_t sB, sC;
    cudaStreamCreateWithFlags(&sB, cudaStreamNonBlocking);
    cudaStreamCreateWithFlags(&sC, cudaStreamNonBlocking);
    cudaEvent_t eZero, eDinv, eG1, eA0, eB2, eAgg1;
    cudaEventCreateWithFlags(&eZero, cudaEventDisableTiming);
    cudaEventCreateWithFlags(&eDinv, cudaEventDisableTiming);
    cudaEventCreateWithFlags(&eG1,   cudaEventDisableTiming);
    cudaEventCreateWithFlags(&eA0,   cudaEventDisableTiming);
    cudaEventCreateWithFlags(&eB2,   cudaEventDisableTiming);
    cudaEventCreateWithFlags(&eAgg1, cudaEventDisableTiming);

    // main stream (0): graph build chain
    k_zero<<<ZN / 256, 256>>>();
    cudaEventRecord(eZero, 0);

    // stream C: attn0 — only needs d_g=0 and x
    cudaStreamWaitEvent(sC, eZero, 0);
    k_attn<IN_F, H1><<<BB, 256, 0, sC>>>(x, hostidx, a0W, a0b, f0W, f0b, g0W, g0b);
    cudaEventRecord(eA0, sC);

    k_count_mh<<<(EE + 255) / 256, 256>>>(dst, hostidx);
    k_dinv<<<NN / 256, 256>>>();
    cudaEventRecord(eDinv, 0);

    // stream B: gemm1 — needs dinv only; runs under scan/fill/mklist
    cudaStreamWaitEvent(sB, eDinv, 0);
    k_gemm1<<<NN / G1R, 256, 0, sB>>>(x, W1);
    cudaEventRecord(eG1, sB);

    k_scan1<<<NB, 256>>>();
    k_scan2<<<1, 256>>>();
    k_scan3<<<NB, 256>>>();
    k_fill_me<<<(EE + 255) / 256, 256>>>(src, dst);
    k_mklist<<<NN / 256, 256>>>();

    // agg1 needs gemm1 (xw) + graph build
    cudaStreamWaitEvent(0, eG1, 0);
    k_agg1<<<NN, 256>>>(b1);
    cudaEventRecord(eAgg1, 0);

    // stream B: gemm2 + agg2 — parallel with attn1 (independent of g)
    cudaStreamWaitEvent(sB, eAgg1, 0);
    k_gemm2<<<(NN + G2R - 1) / G2R, 256, 0, sB>>>(W2);
    k_agg2<<<BB * NHOST, 64, 0, sB>>>(hostidx, b2);
    cudaEventRecord(eB2, sB);

    // main: attn1 (512-thread k-split) — needs x1 (main) + g (attn0 via eA0)
    cudaStreamWaitEvent(0, eA0, 0);
    k_attn1<<<BB, 512>>>(x1_ptr, hostidx, a1W, a1b, f1W, f1b, g1W, g1b);

    // attn2+head — needs g (main order) + x2h (eB2)
    cudaStreamWaitEvent(0, eB2, 0);
    k_attn2h<<<BB, 256>>>(x2h_ptr, a2W, a2b, f2W, f2b, g2W, g2b,
                          o1W, o1b, o2W, o2b, out);

    cudaEventDestroy(eZero);
    cudaEventDestroy(eDinv);
    cudaEventDestroy(eG1);
    cudaEventDestroy(eA0);
    cudaEventDestroy(eB2);
    cudaEventDestroy(eAgg1);
    cudaStreamDestroy(sB);
    cudaStreamDestroy(sC);
}